// round 7
// baseline (speedup 1.0000x reference)
#include <cuda_runtime.h>
#include <math.h>

#define BB 16
#define LL 1024
#define CC 512
#define PP 64
#define HH 8
#define DKK 64
#define HD 512
#define FF 2048

// ------------------------- device scratch -------------------------
__device__ float g_pscore[BB * LL * PP];           // (B,L,P)
__device__ float g_pAT[BB * PP * LL];              // (B,P,L)
__device__ float g_PS[BB * PP * (LL + 1)];         // prefix sums over m
__device__ float g_kxp[BB * PP * CC];
__device__ float g_vxp[BB * PP * CC];
__device__ float g_q[BB * LL * HD];
__device__ float g_k[BB * PP * HD];
__device__ float g_v[BB * PP * HD];
__device__ float g_scores[BB * HH * PP * LL];      // (B,H,P,L)
__device__ float g_z[BB * LL * HD];
__device__ float g_y1[BB * LL * CC];
__device__ float g_z1[BB * LL * CC];
__device__ float g_h1[(long)BB * LL * FF];
__device__ float g_y2[BB * LL * CC];

// relative position bucket distance ranges (t=0..14)
__constant__ int c_lo[15] = {0,1,2,3,4,5,6,7, 9,11,15,23,39, 71,135};
__constant__ int c_hi[15] = {0,1,2,3,4,5,6,8,10,14,22,38,70,134,1023};

__device__ __forceinline__ float gelu_exact(float x) {
    return 0.5f * x * (1.0f + erff(x * 0.70710678118654752f));
}

// ------------------------- generic SGEMM -------------------------
// C[M,N] = A[M,K] @ W[K,N] (+bias)(+res)(gelu). Row-major. Shapes must be
// multiples of the tile sizes (they are, for every call below).
// EPI: 0 = none, 1 = +bias, 2 = +bias+res, 3 = +bias then gelu
template <int BM, int BN, int BK, int TM, int TN, int EPI>
__global__ void __launch_bounds__(256) sgemm(
    const float* __restrict__ A, const float* __restrict__ W,
    const float* __restrict__ bias, const float* __restrict__ res,
    float* __restrict__ C, int M, int N, int K,
    long sA, long sB, long sC)
{
    __shared__ float As[BK][BM + 4];
    __shared__ float Bs[BK][BN];
    const int tid = threadIdx.x;
    const int bz = blockIdx.z;
    A += (long)bz * sA;
    W += (long)bz * sB;
    C += (long)bz * sC;
    const int m0 = blockIdx.y * BM;
    const int n0 = blockIdx.x * BN;

    const int tx = tid % (BN / TN);
    const int ty = tid / (BN / TN);

    float acc[TM][TN];
#pragma unroll
    for (int i = 0; i < TM; i++)
#pragma unroll
        for (int j = 0; j < TN; j++) acc[i][j] = 0.f;

    for (int k0 = 0; k0 < K; k0 += BK) {
        // load A tile (BM x BK), store transposed
#pragma unroll
        for (int it = 0; it < BM * BK / 1024; ++it) {
            int f = tid + it * 256;
            int row = f / (BK / 4);
            int c4 = f % (BK / 4);
            float4 v = *(const float4*)&A[(long)(m0 + row) * K + k0 + c4 * 4];
            As[c4 * 4 + 0][row] = v.x;
            As[c4 * 4 + 1][row] = v.y;
            As[c4 * 4 + 2][row] = v.z;
            As[c4 * 4 + 3][row] = v.w;
        }
        // load B tile (BK x BN)
#pragma unroll
        for (int it = 0; it < BK * BN / 1024; ++it) {
            int f = tid + it * 256;
            int row = f / (BN / 4);
            int c4 = f % (BN / 4);
            *(float4*)&Bs[row][c4 * 4] =
                *(const float4*)&W[(long)(k0 + row) * N + n0 + c4 * 4];
        }
        __syncthreads();
#pragma unroll
        for (int kk = 0; kk < BK; ++kk) {
            float a[TM], bfrag[TN];
#pragma unroll
            for (int i = 0; i < TM / 4; i++)
                ((float4*)a)[i] = *(const float4*)&As[kk][ty * TM + i * 4];
#pragma unroll
            for (int j = 0; j < TN / 4; j++)
                ((float4*)bfrag)[j] = *(const float4*)&Bs[kk][tx * TN + j * 4];
#pragma unroll
            for (int i = 0; i < TM; i++)
#pragma unroll
                for (int j = 0; j < TN; j++) acc[i][j] += a[i] * bfrag[j];
        }
        __syncthreads();
    }

#pragma unroll
    for (int i = 0; i < TM; i++) {
        int row = m0 + ty * TM + i;
#pragma unroll
        for (int j = 0; j < TN; j++) {
            int col = n0 + tx * TN + j;
            float v = acc[i][j];
            if (EPI >= 1) v += bias[col];
            long idx = (long)row * N + col;
            if (EPI == 2) v += res[idx];
            if (EPI == 3) v = gelu_exact(v);
            C[idx] = v;
        }
    }
}

// --------------- pseudo-token softmax over L + prefix scan ---------------
// one block per (p, b). Produces pAT (B,P,L) and PS (B,P,L+1).
__global__ void __launch_bounds__(256) softmax_scan_kernel(
    const float* __restrict__ pscore, const int* __restrict__ maskPAD,
    float* __restrict__ pAT, float* __restrict__ PS)
{
    const int p = blockIdx.x, b = blockIdx.y;
    const int tid = threadIdx.x;
    __shared__ float red[256];

    float loc[4];
    float mx = -3.0e38f;
#pragma unroll
    for (int i = 0; i < 4; i++) {
        int l = tid * 4 + i;
        float v = pscore[((long)(b * LL + l)) * PP + p];
        if (maskPAD[(long)b * LL * LL + l] == 0) v = -32768.0f;
        loc[i] = v;
        mx = fmaxf(mx, v);
    }
    red[tid] = mx;
    __syncthreads();
    for (int s = 128; s > 0; s >>= 1) {
        if (tid < s) red[tid] = fmaxf(red[tid], red[tid + s]);
        __syncthreads();
    }
    mx = red[0];
    __syncthreads();

    float tsum = 0.f;
#pragma unroll
    for (int i = 0; i < 4; i++) {
        loc[i] = expf(loc[i] - mx);
        tsum += loc[i];
    }
    red[tid] = tsum;
    __syncthreads();
    // Hillis-Steele inclusive scan over thread sums
    for (int off = 1; off < 256; off <<= 1) {
        float t = (tid >= off) ? red[tid - off] : 0.f;
        __syncthreads();
        red[tid] += t;
        __syncthreads();
    }
    float total = red[255];
    float excl = red[tid] - tsum;
    float inv = 1.0f / total;

    float* pa = pAT + ((long)(b * PP + p)) * LL;
    float* ps = PS + ((long)(b * PP + p)) * (LL + 1);
    if (tid == 0) ps[0] = 0.f;
    float run = excl;
#pragma unroll
    for (int i = 0; i < 4; i++) {
        int l = tid * 4 + i;
        pa[l] = loc[i] * inv;
        run += loc[i];
        ps[l + 1] = run * inv;
    }
}

// ------------------------- attention scores -------------------------
// scores[b,h,p,l] = (q[b,l,h,:] . k[b,p,h,:]) / 8
__global__ void __launch_bounds__(256) scores_kernel(
    const float* __restrict__ q, const float* __restrict__ k,
    float* __restrict__ scores)
{
    const int lt = blockIdx.x;  // L/64
    const int h = blockIdx.y, b = blockIdx.z;
    const int l0 = lt * 64;
    const int tid = threadIdx.x;
    __shared__ float sk[64][65];  // [d][p]
    __shared__ float sq[64][65];  // [d][l]

#pragma unroll
    for (int it = 0; it < 4; ++it) {
        int f = tid + it * 256;
        int p = f / 16, d4 = f % 16;
        float4 v = *(const float4*)&k[((long)(b * PP + p)) * HD + h * 64 + d4 * 4];
        sk[d4 * 4 + 0][p] = v.x; sk[d4 * 4 + 1][p] = v.y;
        sk[d4 * 4 + 2][p] = v.z; sk[d4 * 4 + 3][p] = v.w;
    }
#pragma unroll
    for (int it = 0; it < 4; ++it) {
        int f = tid + it * 256;
        int l = f / 16, d4 = f % 16;
        float4 v = *(const float4*)&q[((long)(b * LL + l0 + l)) * HD + h * 64 + d4 * 4];
        sq[d4 * 4 + 0][l] = v.x; sq[d4 * 4 + 1][l] = v.y;
        sq[d4 * 4 + 2][l] = v.z; sq[d4 * 4 + 3][l] = v.w;
    }
    __syncthreads();

    const int ty = tid / 16;  // p group
    const int tx = tid % 16;  // l group
    float acc[4][4] = {};
#pragma unroll
    for (int d = 0; d < 64; d++) {
        float a[4], bb[4];
#pragma unroll
        for (int i = 0; i < 4; i++) a[i] = sk[d][ty * 4 + i];
#pragma unroll
        for (int j = 0; j < 4; j++) bb[j] = sq[d][tx * 4 + j];
#pragma unroll
        for (int i = 0; i < 4; i++)
#pragma unroll
            for (int j = 0; j < 4; j++) acc[i][j] += a[i] * bb[j];
    }
#pragma unroll
    for (int i = 0; i < 4; i++) {
        int p = ty * 4 + i;
#pragma unroll
        for (int j = 0; j < 4; j++) {
            int l = tx * 4 + j;
            scores[(((long)(b * HH + h)) * PP + p) * LL + l0 + l] = acc[i][j] * 0.125f;
        }
    }
}

// ------------------------- relative-position bias -------------------------
// scores[b,h,p,l] = scores*Kb + bb where Kb/bb come from 15 banded sums of pA.
__global__ void __launch_bounds__(256) relbias_kernel(
    const float* __restrict__ PS, const float* __restrict__ pAT,
    const float* __restrict__ embK, const float* __restrict__ embB,
    float* __restrict__ scores)
{
    const int l = blockIdx.x * 256 + threadIdx.x;
    const int p = blockIdx.y, b = blockIdx.z;
    __shared__ float sK[120], sB[120];
    if (threadIdx.x < 120) {
        sK[threadIdx.x] = embK[threadIdx.x];
        sB[threadIdx.x] = embB[threadIdx.x];
    }
    __syncthreads();

    const float* ps = PS + ((long)(b * PP + p)) * (LL + 1);
    float S[15];
    S[0] = pAT[((long)(b * PP + p)) * LL + l];
#pragma unroll
    for (int t = 1; t < 15; t++) {
        int lo = c_lo[t], hi = c_hi[t];
        float s = 0.f;
        int a1 = l - lo;
        if (a1 >= 0) {
            int a0 = l - hi; if (a0 < 0) a0 = 0;
            s += ps[a1 + 1] - ps[a0];
        }
        int b0 = l + lo;
        if (b0 < LL) {
            int b1 = l + hi; if (b1 > LL - 1) b1 = LL - 1;
            s += ps[b1 + 1] - ps[b0];
        }
        S[t] = s;
    }
#pragma unroll
    for (int h = 0; h < HH; h++) {
        float kb = 0.f, bb = 0.f;
#pragma unroll
        for (int t = 0; t < 15; t++) {
            kb += S[t] * sK[t * HH + h];
            bb += S[t] * sB[t * HH + h];
        }
        long idx = (((long)(b * HH + h)) * PP + p) * LL + l;
        scores[idx] = scores[idx] * kb + bb;
    }
}

// ------------------------- softmax over P (=64) -------------------------
__global__ void __launch_bounds__(256) softmaxP_kernel(float* __restrict__ scores)
{
    const long l = blockIdx.x * 256 + threadIdx.x;
    const int bh = blockIdx.y;
    float* base = scores + (long)bh * PP * LL + l;
    float v[PP];
    float mx = -3.0e38f;
#pragma unroll
    for (int p = 0; p < PP; p++) {
        v[p] = base[(long)p * LL];
        mx = fmaxf(mx, v[p]);
    }
    float s = 0.f;
#pragma unroll
    for (int p = 0; p < PP; p++) {
        v[p] = expf(v[p] - mx);
        s += v[p];
    }
    float inv = 1.0f / s;
#pragma unroll
    for (int p = 0; p < PP; p++) base[(long)p * LL] = v[p] * inv;
}

// ------------------------- z = alpha @ v -------------------------
// z[b, l, h*64+d] = sum_p alpha[b,h,p,l] * v[b,p,h*64+d]
__global__ void __launch_bounds__(256) zhead_kernel(
    const float* __restrict__ alpha, const float* __restrict__ v,
    float* __restrict__ z)
{
    const int lt = blockIdx.x;
    const int h = blockIdx.y, b = blockIdx.z;
    const int l0 = lt * 64;
    const int tid = threadIdx.x;
    __shared__ float sa[64][64];  // [p][l]
    __shared__ float sv[64][64];  // [p][d]

#pragma unroll
    for (int it = 0; it < 4; ++it) {
        int f = tid + it * 256;
        int p = f / 16, l4 = f % 16;
        *(float4*)&sa[p][l4 * 4] =
            *(const float4*)&alpha[(((long)(b * HH + h)) * PP + p) * LL + l0 + l4 * 4];
    }
#pragma unroll
    for (int it = 0; it < 4; ++it) {
        int f = tid + it * 256;
        int p = f / 16, d4 = f % 16;
        *(float4*)&sv[p][d4 * 4] =
            *(const float4*)&v[((long)(b * PP + p)) * HD + h * 64 + d4 * 4];
    }
    __syncthreads();

    const int ty = tid / 16;  // l group
    const int tx = tid % 16;  // d group
    float acc[4][4] = {};
#pragma unroll
    for (int p = 0; p < 64; p++) {
        float a[4], bb[4];
#pragma unroll
        for (int i = 0; i < 4; i++) a[i] = sa[p][ty * 4 + i];
#pragma unroll
        for (int j = 0; j < 4; j++) bb[j] = sv[p][tx * 4 + j];
#pragma unroll
        for (int i = 0; i < 4; i++)
#pragma unroll
            for (int j = 0; j < 4; j++) acc[i][j] += a[i] * bb[j];
    }
#pragma unroll
    for (int i = 0; i < 4; i++) {
        int l = l0 + ty * 4 + i;
#pragma unroll
        for (int j = 0; j < 4; j++) {
            z[((long)(b * LL + l)) * HD + h * 64 + tx * 4 + j] = acc[i][j];
        }
    }
}

// ------------------------- layernorm (row of 512) -------------------------
__global__ void __launch_bounds__(256) ln_kernel(
    const float* __restrict__ x, const float* __restrict__ g,
    const float* __restrict__ b, float* __restrict__ out)
{
    const int row = blockIdx.x;
    const int tid = threadIdx.x;
    __shared__ float red[256];
    float2 v = ((const float2*)(x + (long)row * CC))[tid];

    red[tid] = v.x + v.y;
    __syncthreads();
    for (int s = 128; s > 0; s >>= 1) {
        if (tid < s) red[tid] += red[tid + s];
        __syncthreads();
    }
    float mean = red[0] * (1.0f / CC);
    __syncthreads();

    float dx = v.x - mean, dy = v.y - mean;
    red[tid] = dx * dx + dy * dy;
    __syncthreads();
    for (int s = 128; s > 0; s >>= 1) {
        if (tid < s) red[tid] += red[tid + s];
        __syncthreads();
    }
    float var = red[0] * (1.0f / CC);
    float rstd = rsqrtf(var + 1e-5f);

    int c = tid * 2;
    float2 o;
    o.x = dx * rstd * g[c] + b[c];
    o.y = dy * rstd * g[c + 1] + b[c + 1];
    ((float2*)(out + (long)row * CC))[tid] = o;
}

// ------------------------- host launch -------------------------
extern "C" void kernel_launch(void* const* d_in, const int* in_sizes, int n_in,
                              void* d_out, int out_size)
{
    const float* qx = (const float*)d_in[0];
    const float* kx = (const float*)d_in[1];
    const float* vx = (const float*)d_in[2];
    const int* maskPAD = (const int*)d_in[3];
    const float* Wp = (const float*)d_in[4];
    const float* bp = (const float*)d_in[5];
    const float* WQ = (const float*)d_in[6];
    const float* bQ = (const float*)d_in[7];
    const float* WK = (const float*)d_in[8];
    const float* bK = (const float*)d_in[9];
    const float* WV = (const float*)d_in[10];
    const float* bV = (const float*)d_in[11];
    const float* WO = (const float*)d_in[12];
    const float* bO = (const float*)d_in[13];
    const float* embK = (const float*)d_in[14];
    const float* embB = (const float*)d_in[15];
    const float* ln1_g = (const float*)d_in[16];
    const float* ln1_b = (const float*)d_in[17];
    const float* ln2_g = (const float*)d_in[18];
    const float* ln2_b = (const float*)d_in[19];
    const float* W1 = (const float*)d_in[20];
    const float* b1 = (const float*)d_in[21];
    const float* W2 = (const float*)d_in[22];
    const float* b2 = (const float*)d_in[23];
    float* out = (float*)d_out;

    float *d_pscore, *d_pAT, *d_PS, *d_kxp, *d_vxp, *d_q, *d_k, *d_v;
    float *d_scores, *d_z, *d_y1, *d_z1, *d_h1, *d_y2;
    cudaGetSymbolAddress((void**)&d_pscore, g_pscore);
    cudaGetSymbolAddress((void**)&d_pAT, g_pAT);
    cudaGetSymbolAddress((void**)&d_PS, g_PS);
    cudaGetSymbolAddress((void**)&d_kxp, g_kxp);
    cudaGetSymbolAddress((void**)&d_vxp, g_vxp);
    cudaGetSymbolAddress((void**)&d_q, g_q);
    cudaGetSymbolAddress((void**)&d_k, g_k);
    cudaGetSymbolAddress((void**)&d_v, g_v);
    cudaGetSymbolAddress((void**)&d_scores, g_scores);
    cudaGetSymbolAddress((void**)&d_z, g_z);
    cudaGetSymbolAddress((void**)&d_y1, g_y1);
    cudaGetSymbolAddress((void**)&d_z1, g_z1);
    cudaGetSymbolAddress((void**)&d_h1, g_h1);
    cudaGetSymbolAddress((void**)&d_y2, g_y2);

    const int M = BB * LL;  // 16384

    // 1) pScore = vx @ Wp + bp           (16384 x 64, K=512)
    sgemm<128, 64, 16, 8, 4, 1><<<dim3(1, M / 128, 1), 256>>>(
        vx, Wp, bp, nullptr, d_pscore, M, PP, CC, 0, 0, 0);

    // 2) softmax over L + prefix scan
    softmax_scan_kernel<<<dim3(PP, BB), 256>>>(d_pscore, maskPAD, d_pAT, d_PS);

    // 3,4) kxp/vxp = pAT @ {kx,vx}       (batched: 64 x 512, K=1024)
    sgemm<64, 64, 16, 4, 4, 0><<<dim3(CC / 64, 1, BB), 256>>>(
        d_pAT, kx, nullptr, nullptr, d_kxp, PP, CC, LL,
        (long)PP * LL, (long)LL * CC, (long)PP * CC);
    sgemm<64, 64, 16, 4, 4, 0><<<dim3(CC / 64, 1, BB), 256>>>(
        d_pAT, vx, nullptr, nullptr, d_vxp, PP, CC, LL,
        (long)PP * LL, (long)LL * CC, (long)PP * CC);

    // 5) q = qx @ WQ + bQ                (16384 x 512, K=512)
    sgemm<128, 128, 16, 8, 8, 1><<<dim3(HD / 128, M / 128, 1), 256>>>(
        qx, WQ, bQ, nullptr, d_q, M, HD, CC, 0, 0, 0);

    // 6,7) k/v = kxp/vxp @ WK/WV + b     (1024 x 512, K=512)
    sgemm<128, 128, 16, 8, 8, 1><<<dim3(HD / 128, (BB * PP) / 128, 1), 256>>>(
        d_kxp, WK, bK, nullptr, d_k, BB * PP, HD, CC, 0, 0, 0);
    sgemm<128, 128, 16, 8, 8, 1><<<dim3(HD / 128, (BB * PP) / 128, 1), 256>>>(
        d_vxp, WV, bV, nullptr, d_v, BB * PP, HD, CC, 0, 0, 0);

    // 8) scores (B,H,P,L)
    scores_kernel<<<dim3(LL / 64, HH, BB), 256>>>(d_q, d_k, d_scores);

    // 9) relative-position bias via banded prefix sums
    relbias_kernel<<<dim3(LL / 256, PP, BB), 256>>>(d_PS, d_pAT, embK, embB, d_scores);

    // 10) softmax over P
    softmaxP_kernel<<<dim3(LL / 256, BB * HH), 256>>>(d_scores);

    // 11) z = alpha @ v
    zhead_kernel<<<dim3(LL / 64, HH, BB), 256>>>(d_scores, d_v, d_z);

    // 12) y1 = z @ WO + bO + vx
    sgemm<128, 128, 16, 8, 8, 2><<<dim3(CC / 128, M / 128, 1), 256>>>(
        d_z, WO, bO, vx, d_y1, M, CC, HD, 0, 0, 0);

    // 13) z1 = LN1(y1)
    ln_kernel<<<M, 256>>>(d_y1, ln1_g, ln1_b, d_z1);

    // 14) h1 = gelu(z1 @ W1 + b1)        (16384 x 2048, K=512)
    sgemm<128, 128, 16, 8, 8, 3><<<dim3(FF / 128, M / 128, 1), 256>>>(
        d_z1, W1, b1, nullptr, d_h1, M, FF, CC, 0, 0, 0);

    // 15) y2 = h1 @ W2 + b2 + z1         (16384 x 512, K=2048)
    sgemm<128, 128, 16, 8, 8, 2><<<dim3(CC / 128, M / 128, 1), 256>>>(
        d_h1, W2, b2, d_z1, d_y2, M, CC, FF, 0, 0, 0);

    // 16) out = LN2(y2)
    ln_kernel<<<M, 256>>>(d_y2, ln2_g, ln2_b, out);
}

// round 8
// speedup vs baseline: 1.0023x; 1.0023x over previous
#include <cuda_runtime.h>
#include <math.h>

#define BB 16
#define LL 1024
#define CC 512
#define PP 64
#define HH 8
#define DKK 64
#define HD 512
#define FF 2048

// ------------------------- device scratch -------------------------
__device__ float g_pscore[BB * LL * PP];           // (B,L,P)
__device__ float g_pAT[BB * PP * LL];              // (B,P,L)
__device__ float g_PS[BB * PP * (LL + 1)];         // prefix sums over m
__device__ float g_kxp[BB * PP * CC];
__device__ float g_vxp[BB * PP * CC];
__device__ float g_q[BB * LL * HD];
__device__ float g_k[BB * PP * HD];
__device__ float g_v[BB * PP * HD];
__device__ float g_scores[BB * HH * PP * LL];      // (B,H,P,L)
__device__ float g_z[BB * LL * HD];
__device__ float g_y1[BB * LL * CC];
__device__ float g_z1[BB * LL * CC];
__device__ float g_h1[(long)BB * LL * FF];
__device__ float g_y2[BB * LL * CC];

// relative position bucket distance ranges (t=0..14)
__constant__ int c_lo[15] = {0,1,2,3,4,5,6,7, 9,11,15,23,39, 71,135};
__constant__ int c_hi[15] = {0,1,2,3,4,5,6,8,10,14,22,38,70,134,1023};

__device__ __forceinline__ float gelu_exact(float x) {
    return 0.5f * x * (1.0f + erff(x * 0.70710678118654752f));
}

// ------------------------- generic SGEMM -------------------------
// C[M,N] = A[M,K] @ W[K,N] (+bias)(+res)(gelu). Row-major. Shapes must be
// multiples of the tile sizes (they are, for every call below).
// EPI: 0 = none, 1 = +bias, 2 = +bias+res, 3 = +bias then gelu
template <int BM, int BN, int BK, int TM, int TN, int EPI>
__global__ void __launch_bounds__(256) sgemm(
    const float* __restrict__ A, const float* __restrict__ W,
    const float* __restrict__ bias, const float* __restrict__ res,
    float* __restrict__ C, int M, int N, int K,
    long sA, long sB, long sC)
{
    __shared__ float As[BK][BM + 4];
    __shared__ float Bs[BK][BN];
    const int tid = threadIdx.x;
    const int bz = blockIdx.z;
    A += (long)bz * sA;
    W += (long)bz * sB;
    C += (long)bz * sC;
    const int m0 = blockIdx.y * BM;
    const int n0 = blockIdx.x * BN;

    const int tx = tid % (BN / TN);
    const int ty = tid / (BN / TN);

    float acc[TM][TN];
#pragma unroll
    for (int i = 0; i < TM; i++)
#pragma unroll
        for (int j = 0; j < TN; j++) acc[i][j] = 0.f;

    for (int k0 = 0; k0 < K; k0 += BK) {
        // load A tile (BM x BK), store transposed
#pragma unroll
        for (int it = 0; it < BM * BK / 1024; ++it) {
            int f = tid + it * 256;
            int row = f / (BK / 4);
            int c4 = f % (BK / 4);
            float4 v = *(const float4*)&A[(long)(m0 + row) * K + k0 + c4 * 4];
            As[c4 * 4 + 0][row] = v.x;
            As[c4 * 4 + 1][row] = v.y;
            As[c4 * 4 + 2][row] = v.z;
            As[c4 * 4 + 3][row] = v.w;
        }
        // load B tile (BK x BN)
#pragma unroll
        for (int it = 0; it < BK * BN / 1024; ++it) {
            int f = tid + it * 256;
            int row = f / (BN / 4);
            int c4 = f % (BN / 4);
            *(float4*)&Bs[row][c4 * 4] =
                *(const float4*)&W[(long)(k0 + row) * N + n0 + c4 * 4];
        }
        __syncthreads();
#pragma unroll
        for (int kk = 0; kk < BK; ++kk) {
            float a[TM], bfrag[TN];
#pragma unroll
            for (int i = 0; i < TM / 4; i++)
                ((float4*)a)[i] = *(const float4*)&As[kk][ty * TM + i * 4];
#pragma unroll
            for (int j = 0; j < TN / 4; j++)
                ((float4*)bfrag)[j] = *(const float4*)&Bs[kk][tx * TN + j * 4];
#pragma unroll
            for (int i = 0; i < TM; i++)
#pragma unroll
                for (int j = 0; j < TN; j++) acc[i][j] += a[i] * bfrag[j];
        }
        __syncthreads();
    }

#pragma unroll
    for (int i = 0; i < TM; i++) {
        int row = m0 + ty * TM + i;
#pragma unroll
        for (int j = 0; j < TN; j++) {
            int col = n0 + tx * TN + j;
            float v = acc[i][j];
            if (EPI >= 1) v += bias[col];
            long idx = (long)row * N + col;
            if (EPI == 2) v += res[idx];
            if (EPI == 3) v = gelu_exact(v);
            C[idx] = v;
        }
    }
}

// --------------- pseudo-token softmax over L + prefix scan ---------------
// one block per (p, b). Produces pAT (B,P,L) and PS (B,P,L+1).
__global__ void __launch_bounds__(256) softmax_scan_kernel(
    const float* __restrict__ pscore, const int* __restrict__ maskPAD,
    float* __restrict__ pAT, float* __restrict__ PS)
{
    const int p = blockIdx.x, b = blockIdx.y;
    const int tid = threadIdx.x;
    __shared__ float red[256];

    float loc[4];
    float mx = -3.0e38f;
#pragma unroll
    for (int i = 0; i < 4; i++) {
        int l = tid * 4 + i;
        float v = pscore[((long)(b * LL + l)) * PP + p];
        if (maskPAD[(long)b * LL * LL + l] == 0) v = -32768.0f;
        loc[i] = v;
        mx = fmaxf(mx, v);
    }
    red[tid] = mx;
    __syncthreads();
    for (int s = 128; s > 0; s >>= 1) {
        if (tid < s) red[tid] = fmaxf(red[tid], red[tid + s]);
        __syncthreads();
    }
    mx = red[0];
    __syncthreads();

    float tsum = 0.f;
#pragma unroll
    for (int i = 0; i < 4; i++) {
        loc[i] = expf(loc[i] - mx);
        tsum += loc[i];
    }
    red[tid] = tsum;
    __syncthreads();
    // Hillis-Steele inclusive scan over thread sums
    for (int off = 1; off < 256; off <<= 1) {
        float t = (tid >= off) ? red[tid - off] : 0.f;
        __syncthreads();
        red[tid] += t;
        __syncthreads();
    }
    float total = red[255];
    float excl = red[tid] - tsum;
    float inv = 1.0f / total;

    float* pa = pAT + ((long)(b * PP + p)) * LL;
    float* ps = PS + ((long)(b * PP + p)) * (LL + 1);
    if (tid == 0) ps[0] = 0.f;
    float run = excl;
#pragma unroll
    for (int i = 0; i < 4; i++) {
        int l = tid * 4 + i;
        pa[l] = loc[i] * inv;
        run += loc[i];
        ps[l + 1] = run * inv;
    }
}

// ------------------------- attention scores -------------------------
// scores[b,h,p,l] = (q[b,l,h,:] . k[b,p,h,:]) / 8
__global__ void __launch_bounds__(256) scores_kernel(
    const float* __restrict__ q, const float* __restrict__ k,
    float* __restrict__ scores)
{
    const int lt = blockIdx.x;  // L/64
    const int h = blockIdx.y, b = blockIdx.z;
    const int l0 = lt * 64;
    const int tid = threadIdx.x;
    __shared__ float sk[64][65];  // [d][p]
    __shared__ float sq[64][65];  // [d][l]

#pragma unroll
    for (int it = 0; it < 4; ++it) {
        int f = tid + it * 256;
        int p = f / 16, d4 = f % 16;
        float4 v = *(const float4*)&k[((long)(b * PP + p)) * HD + h * 64 + d4 * 4];
        sk[d4 * 4 + 0][p] = v.x; sk[d4 * 4 + 1][p] = v.y;
        sk[d4 * 4 + 2][p] = v.z; sk[d4 * 4 + 3][p] = v.w;
    }
#pragma unroll
    for (int it = 0; it < 4; ++it) {
        int f = tid + it * 256;
        int l = f / 16, d4 = f % 16;
        float4 v = *(const float4*)&q[((long)(b * LL + l0 + l)) * HD + h * 64 + d4 * 4];
        sq[d4 * 4 + 0][l] = v.x; sq[d4 * 4 + 1][l] = v.y;
        sq[d4 * 4 + 2][l] = v.z; sq[d4 * 4 + 3][l] = v.w;
    }
    __syncthreads();

    const int ty = tid / 16;  // p group
    const int tx = tid % 16;  // l group
    float acc[4][4] = {};
#pragma unroll
    for (int d = 0; d < 64; d++) {
        float a[4], bb[4];
#pragma unroll
        for (int i = 0; i < 4; i++) a[i] = sk[d][ty * 4 + i];
#pragma unroll
        for (int j = 0; j < 4; j++) bb[j] = sq[d][tx * 4 + j];
#pragma unroll
        for (int i = 0; i < 4; i++)
#pragma unroll
            for (int j = 0; j < 4; j++) acc[i][j] += a[i] * bb[j];
    }
#pragma unroll
    for (int i = 0; i < 4; i++) {
        int p = ty * 4 + i;
#pragma unroll
        for (int j = 0; j < 4; j++) {
            int l = tx * 4 + j;
            scores[(((long)(b * HH + h)) * PP + p) * LL + l0 + l] = acc[i][j] * 0.125f;
        }
    }
}

// ------------------------- relative-position bias -------------------------
// scores[b,h,p,l] = scores*Kb + bb where Kb/bb come from 15 banded sums of pA.
__global__ void __launch_bounds__(256) relbias_kernel(
    const float* __restrict__ PS, const float* __restrict__ pAT,
    const float* __restrict__ embK, const float* __restrict__ embB,
    float* __restrict__ scores)
{
    const int l = blockIdx.x * 256 + threadIdx.x;
    const int p = blockIdx.y, b = blockIdx.z;
    __shared__ float sK[120], sB[120];
    if (threadIdx.x < 120) {
        sK[threadIdx.x] = embK[threadIdx.x];
        sB[threadIdx.x] = embB[threadIdx.x];
    }
    __syncthreads();

    const float* ps = PS + ((long)(b * PP + p)) * (LL + 1);
    float S[15];
    S[0] = pAT[((long)(b * PP + p)) * LL + l];
#pragma unroll
    for (int t = 1; t < 15; t++) {
        int lo = c_lo[t], hi = c_hi[t];
        float s = 0.f;
        int a1 = l - lo;
        if (a1 >= 0) {
            int a0 = l - hi; if (a0 < 0) a0 = 0;
            s += ps[a1 + 1] - ps[a0];
        }
        int b0 = l + lo;
        if (b0 < LL) {
            int b1 = l + hi; if (b1 > LL - 1) b1 = LL - 1;
            s += ps[b1 + 1] - ps[b0];
        }
        S[t] = s;
    }
#pragma unroll
    for (int h = 0; h < HH; h++) {
        float kb = 0.f, bb = 0.f;
#pragma unroll
        for (int t = 0; t < 15; t++) {
            kb += S[t] * sK[t * HH + h];
            bb += S[t] * sB[t * HH + h];
        }
        long idx = (((long)(b * HH + h)) * PP + p) * LL + l;
        scores[idx] = scores[idx] * kb + bb;
    }
}

// ------------------------- softmax over P (=64) -------------------------
__global__ void __launch_bounds__(256) softmaxP_kernel(float* __restrict__ scores)
{
    const long l = blockIdx.x * 256 + threadIdx.x;
    const int bh = blockIdx.y;
    float* base = scores + (long)bh * PP * LL + l;
    float v[PP];
    float mx = -3.0e38f;
#pragma unroll
    for (int p = 0; p < PP; p++) {
        v[p] = base[(long)p * LL];
        mx = fmaxf(mx, v[p]);
    }
    float s = 0.f;
#pragma unroll
    for (int p = 0; p < PP; p++) {
        v[p] = expf(v[p] - mx);
        s += v[p];
    }
    float inv = 1.0f / s;
#pragma unroll
    for (int p = 0; p < PP; p++) base[(long)p * LL] = v[p] * inv;
}

// ------------------------- z = alpha @ v -------------------------
// z[b, l, h*64+d] = sum_p alpha[b,h,p,l] * v[b,p,h*64+d]
__global__ void __launch_bounds__(256) zhead_kernel(
    const float* __restrict__ alpha, const float* __restrict__ v,
    float* __restrict__ z)
{
    const int lt = blockIdx.x;
    const int h = blockIdx.y, b = blockIdx.z;
    const int l0 = lt * 64;
    const int tid = threadIdx.x;
    __shared__ float sa[64][64];  // [p][l]
    __shared__ float sv[64][64];  // [p][d]

#pragma unroll
    for (int it = 0; it < 4; ++it) {
        int f = tid + it * 256;
        int p = f / 16, l4 = f % 16;
        *(float4*)&sa[p][l4 * 4] =
            *(const float4*)&alpha[(((long)(b * HH + h)) * PP + p) * LL + l0 + l4 * 4];
    }
#pragma unroll
    for (int it = 0; it < 4; ++it) {
        int f = tid + it * 256;
        int p = f / 16, d4 = f % 16;
        *(float4*)&sv[p][d4 * 4] =
            *(const float4*)&v[((long)(b * PP + p)) * HD + h * 64 + d4 * 4];
    }
    __syncthreads();

    const int ty = tid / 16;  // l group
    const int tx = tid % 16;  // d group
    float acc[4][4] = {};
#pragma unroll
    for (int p = 0; p < 64; p++) {
        float a[4], bb[4];
#pragma unroll
        for (int i = 0; i < 4; i++) a[i] = sa[p][ty * 4 + i];
#pragma unroll
        for (int j = 0; j < 4; j++) bb[j] = sv[p][tx * 4 + j];
#pragma unroll
        for (int i = 0; i < 4; i++)
#pragma unroll
            for (int j = 0; j < 4; j++) acc[i][j] += a[i] * bb[j];
    }
#pragma unroll
    for (int i = 0; i < 4; i++) {
        int l = l0 + ty * 4 + i;
#pragma unroll
        for (int j = 0; j < 4; j++) {
            z[((long)(b * LL + l)) * HD + h * 64 + tx * 4 + j] = acc[i][j];
        }
    }
}

// ------------------------- layernorm (row of 512) -------------------------
__global__ void __launch_bounds__(256) ln_kernel(
    const float* __restrict__ x, const float* __restrict__ g,
    const float* __restrict__ b, float* __restrict__ out)
{
    const int row = blockIdx.x;
    const int tid = threadIdx.x;
    __shared__ float red[256];
    float2 v = ((const float2*)(x + (long)row * CC))[tid];

    red[tid] = v.x + v.y;
    __syncthreads();
    for (int s = 128; s > 0; s >>= 1) {
        if (tid < s) red[tid] += red[tid + s];
        __syncthreads();
    }
    float mean = red[0] * (1.0f / CC);
    __syncthreads();

    float dx = v.x - mean, dy = v.y - mean;
    red[tid] = dx * dx + dy * dy;
    __syncthreads();
    for (int s = 128; s > 0; s >>= 1) {
        if (tid < s) red[tid] += red[tid + s];
        __syncthreads();
    }
    float var = red[0] * (1.0f / CC);
    float rstd = rsqrtf(var + 1e-5f);

    int c = tid * 2;
    float2 o;
    o.x = dx * rstd * g[c] + b[c];
    o.y = dy * rstd * g[c + 1] + b[c + 1];
    ((float2*)(out + (long)row * CC))[tid] = o;
}

// ------------------------- host launch -------------------------
extern "C" void kernel_launch(void* const* d_in, const int* in_sizes, int n_in,
                              void* d_out, int out_size)
{
    const float* qx = (const float*)d_in[0];
    const float* kx = (const float*)d_in[1];
    const float* vx = (const float*)d_in[2];
    const int* maskPAD = (const int*)d_in[3];
    const float* Wp = (const float*)d_in[4];
    const float* bp = (const float*)d_in[5];
    const float* WQ = (const float*)d_in[6];
    const float* bQ = (const float*)d_in[7];
    const float* WK = (const float*)d_in[8];
    const float* bK = (const float*)d_in[9];
    const float* WV = (const float*)d_in[10];
    const float* bV = (const float*)d_in[11];
    const float* WO = (const float*)d_in[12];
    const float* bO = (const float*)d_in[13];
    const float* embK = (const float*)d_in[14];
    const float* embB = (const float*)d_in[15];
    const float* ln1_g = (const float*)d_in[16];
    const float* ln1_b = (const float*)d_in[17];
    const float* ln2_g = (const float*)d_in[18];
    const float* ln2_b = (const float*)d_in[19];
    const float* W1 = (const float*)d_in[20];
    const float* b1 = (const float*)d_in[21];
    const float* W2 = (const float*)d_in[22];
    const float* b2 = (const float*)d_in[23];
    float* out = (float*)d_out;

    float *d_pscore, *d_pAT, *d_PS, *d_kxp, *d_vxp, *d_q, *d_k, *d_v;
    float *d_scores, *d_z, *d_y1, *d_z1, *d_h1, *d_y2;
    cudaGetSymbolAddress((void**)&d_pscore, g_pscore);
    cudaGetSymbolAddress((void**)&d_pAT, g_pAT);
    cudaGetSymbolAddress((void**)&d_PS, g_PS);
    cudaGetSymbolAddress((void**)&d_kxp, g_kxp);
    cudaGetSymbolAddress((void**)&d_vxp, g_vxp);
    cudaGetSymbolAddress((void**)&d_q, g_q);
    cudaGetSymbolAddress((void**)&d_k, g_k);
    cudaGetSymbolAddress((void**)&d_v, g_v);
    cudaGetSymbolAddress((void**)&d_scores, g_scores);
    cudaGetSymbolAddress((void**)&d_z, g_z);
    cudaGetSymbolAddress((void**)&d_y1, g_y1);
    cudaGetSymbolAddress((void**)&d_z1, g_z1);
    cudaGetSymbolAddress((void**)&d_h1, g_h1);
    cudaGetSymbolAddress((void**)&d_y2, g_y2);

    const int M = BB * LL;  // 16384

    // 1) pScore = vx @ Wp + bp           (16384 x 64, K=512)
    sgemm<128, 64, 16, 8, 4, 1><<<dim3(1, M / 128, 1), 256>>>(
        vx, Wp, bp, nullptr, d_pscore, M, PP, CC, 0, 0, 0);

    // 2) softmax over L + prefix scan
    softmax_scan_kernel<<<dim3(PP, BB), 256>>>(d_pscore, maskPAD, d_pAT, d_PS);

    // 3,4) kxp/vxp = pAT @ {kx,vx}       (batched: 64 x 512, K=1024)
    sgemm<64, 64, 16, 4, 4, 0><<<dim3(CC / 64, 1, BB), 256>>>(
        d_pAT, kx, nullptr, nullptr, d_kxp, PP, CC, LL,
        (long)PP * LL, (long)LL * CC, (long)PP * CC);
    sgemm<64, 64, 16, 4, 4, 0><<<dim3(CC / 64, 1, BB), 256>>>(
        d_pAT, vx, nullptr, nullptr, d_vxp, PP, CC, LL,
        (long)PP * LL, (long)LL * CC, (long)PP * CC);

    // 5) q = qx @ WQ + bQ                (16384 x 512, K=512)
    sgemm<128, 128, 16, 8, 8, 1><<<dim3(HD / 128, M / 128, 1), 256>>>(
        qx, WQ, bQ, nullptr, d_q, M, HD, CC, 0, 0, 0);

    // 6,7) k/v = kxp/vxp @ WK/WV + b     (1024 x 512, K=512)
    sgemm<128, 128, 16, 8, 8, 1><<<dim3(HD / 128, (BB * PP) / 128, 1), 256>>>(
        d_kxp, WK, bK, nullptr, d_k, BB * PP, HD, CC, 0, 0, 0);
    sgemm<128, 128, 16, 8, 8, 1><<<dim3(HD / 128, (BB * PP) / 128, 1), 256>>>(
        d_vxp, WV, bV, nullptr, d_v, BB * PP, HD, CC, 0, 0, 0);

    // 8) scores (B,H,P,L)
    scores_kernel<<<dim3(LL / 64, HH, BB), 256>>>(d_q, d_k, d_scores);

    // 9) relative-position bias via banded prefix sums
    relbias_kernel<<<dim3(LL / 256, PP, BB), 256>>>(d_PS, d_pAT, embK, embB, d_scores);

    // 10) softmax over P
    softmaxP_kernel<<<dim3(LL / 256, BB * HH), 256>>>(d_scores);

    // 11) z = alpha @ v
    zhead_kernel<<<dim3(LL / 64, HH, BB), 256>>>(d_scores, d_v, d_z);

    // 12) y1 = z @ WO + bO + vx
    sgemm<128, 128, 16, 8, 8, 2><<<dim3(CC / 128, M / 128, 1), 256>>>(
        d_z, WO, bO, vx, d_y1, M, CC, HD, 0, 0, 0);

    // 13) z1 = LN1(y1)
    ln_kernel<<<M, 256>>>(d_y1, ln1_g, ln1_b, d_z1);

    // 14) h1 = gelu(z1 @ W1 + b1)        (16384 x 2048, K=512)
    sgemm<128, 128, 16, 8, 8, 3><<<dim3(FF / 128, M / 128, 1), 256>>>(
        d_z1, W1, b1, nullptr, d_h1, M, FF, CC, 0, 0, 0);

    // 15) y2 = h1 @ W2 + b2 + z1         (16384 x 512, K=2048)
    sgemm<128, 128, 16, 8, 8, 2><<<dim3(CC / 128, M / 128, 1), 256>>>(
        d_h1, W2, b2, d_z1, d_y2, M, CC, FF, 0, 0, 0);

    // 16) out = LN2(y2)
    ln_kernel<<<M, 256>>>(d_y2, ln2_g, ln2_b, out);
}

// round 11
// speedup vs baseline: 1.0031x; 1.0007x over previous
#include <cuda_runtime.h>
#include <math.h>

#define BB 16
#define LL 1024
#define CC 512
#define PP 64
#define HH 8
#define DKK 64
#define HD 512
#define FF 2048

// ------------------------- device scratch -------------------------
__device__ float g_pscore[BB * LL * PP];           // (B,L,P)
__device__ float g_pAT[BB * PP * LL];              // (B,P,L)
__device__ float g_PS[BB * PP * (LL + 1)];         // prefix sums over m
__device__ float g_kxp[BB * PP * CC];
__device__ float g_vxp[BB * PP * CC];
__device__ float g_q[BB * LL * HD];
__device__ float g_k[BB * PP * HD];
__device__ float g_v[BB * PP * HD];
__device__ float g_scores[BB * HH * PP * LL];      // (B,H,P,L)
__device__ float g_z[BB * LL * HD];
__device__ float g_y1[BB * LL * CC];
__device__ float g_z1[BB * LL * CC];
__device__ float g_h1[(long)BB * LL * FF];
__device__ float g_y2[BB * LL * CC];

// relative position bucket distance ranges (t=0..14)
__constant__ int c_lo[15] = {0,1,2,3,4,5,6,7, 9,11,15,23,39, 71,135};
__constant__ int c_hi[15] = {0,1,2,3,4,5,6,8,10,14,22,38,70,134,1023};

__device__ __forceinline__ float gelu_exact(float x) {
    return 0.5f * x * (1.0f + erff(x * 0.70710678118654752f));
}

// ------------------------- generic SGEMM -------------------------
// C[M,N] = A[M,K] @ W[K,N] (+bias)(+res)(gelu). Row-major. Shapes must be
// multiples of the tile sizes (they are, for every call below).
// EPI: 0 = none, 1 = +bias, 2 = +bias+res, 3 = +bias then gelu
template <int BM, int BN, int BK, int TM, int TN, int EPI>
__global__ void __launch_bounds__(256) sgemm(
    const float* __restrict__ A, const float* __restrict__ W,
    const float* __restrict__ bias, const float* __restrict__ res,
    float* __restrict__ C, int M, int N, int K,
    long sA, long sB, long sC)
{
    __shared__ float As[BK][BM + 4];
    __shared__ float Bs[BK][BN];
    const int tid = threadIdx.x;
    const int bz = blockIdx.z;
    A += (long)bz * sA;
    W += (long)bz * sB;
    C += (long)bz * sC;
    const int m0 = blockIdx.y * BM;
    const int n0 = blockIdx.x * BN;

    const int tx = tid % (BN / TN);
    const int ty = tid / (BN / TN);

    float acc[TM][TN];
#pragma unroll
    for (int i = 0; i < TM; i++)
#pragma unroll
        for (int j = 0; j < TN; j++) acc[i][j] = 0.f;

    for (int k0 = 0; k0 < K; k0 += BK) {
        // load A tile (BM x BK), store transposed
#pragma unroll
        for (int it = 0; it < BM * BK / 1024; ++it) {
            int f = tid + it * 256;
            int row = f / (BK / 4);
            int c4 = f % (BK / 4);
            float4 v = *(const float4*)&A[(long)(m0 + row) * K + k0 + c4 * 4];
            As[c4 * 4 + 0][row] = v.x;
            As[c4 * 4 + 1][row] = v.y;
            As[c4 * 4 + 2][row] = v.z;
            As[c4 * 4 + 3][row] = v.w;
        }
        // load B tile (BK x BN)
#pragma unroll
        for (int it = 0; it < BK * BN / 1024; ++it) {
            int f = tid + it * 256;
            int row = f / (BN / 4);
            int c4 = f % (BN / 4);
            *(float4*)&Bs[row][c4 * 4] =
                *(const float4*)&W[(long)(k0 + row) * N + n0 + c4 * 4];
        }
        __syncthreads();
#pragma unroll
        for (int kk = 0; kk < BK; ++kk) {
            float a[TM], bfrag[TN];
#pragma unroll
            for (int i = 0; i < TM / 4; i++)
                ((float4*)a)[i] = *(const float4*)&As[kk][ty * TM + i * 4];
#pragma unroll
            for (int j = 0; j < TN / 4; j++)
                ((float4*)bfrag)[j] = *(const float4*)&Bs[kk][tx * TN + j * 4];
#pragma unroll
            for (int i = 0; i < TM; i++)
#pragma unroll
                for (int j = 0; j < TN; j++) acc[i][j] += a[i] * bfrag[j];
        }
        __syncthreads();
    }

#pragma unroll
    for (int i = 0; i < TM; i++) {
        int row = m0 + ty * TM + i;
#pragma unroll
        for (int j = 0; j < TN; j++) {
            int col = n0 + tx * TN + j;
            float v = acc[i][j];
            if (EPI >= 1) v += bias[col];
            long idx = (long)row * N + col;
            if (EPI == 2) v += res[idx];
            if (EPI == 3) v = gelu_exact(v);
            C[idx] = v;
        }
    }
}

// --------------- pseudo-token softmax over L + prefix scan ---------------
// one block per (p, b). Produces pAT (B,P,L) and PS (B,P,L+1).
__global__ void __launch_bounds__(256) softmax_scan_kernel(
    const float* __restrict__ pscore, const int* __restrict__ maskPAD,
    float* __restrict__ pAT, float* __restrict__ PS)
{
    const int p = blockIdx.x, b = blockIdx.y;
    const int tid = threadIdx.x;
    __shared__ float red[256];

    float loc[4];
    float mx = -3.0e38f;
#pragma unroll
    for (int i = 0; i < 4; i++) {
        int l = tid * 4 + i;
        float v = pscore[((long)(b * LL + l)) * PP + p];
        if (maskPAD[(long)b * LL * LL + l] == 0) v = -32768.0f;
        loc[i] = v;
        mx = fmaxf(mx, v);
    }
    red[tid] = mx;
    __syncthreads();
    for (int s = 128; s > 0; s >>= 1) {
        if (tid < s) red[tid] = fmaxf(red[tid], red[tid + s]);
        __syncthreads();
    }
    mx = red[0];
    __syncthreads();

    float tsum = 0.f;
#pragma unroll
    for (int i = 0; i < 4; i++) {
        loc[i] = expf(loc[i] - mx);
        tsum += loc[i];
    }
    red[tid] = tsum;
    __syncthreads();
    // Hillis-Steele inclusive scan over thread sums
    for (int off = 1; off < 256; off <<= 1) {
        float t = (tid >= off) ? red[tid - off] : 0.f;
        __syncthreads();
        red[tid] += t;
        __syncthreads();
    }
    float total = red[255];
    float excl = red[tid] - tsum;
    float inv = 1.0f / total;

    float* pa = pAT + ((long)(b * PP + p)) * LL;
    float* ps = PS + ((long)(b * PP + p)) * (LL + 1);
    if (tid == 0) ps[0] = 0.f;
    float run = excl;
#pragma unroll
    for (int i = 0; i < 4; i++) {
        int l = tid * 4 + i;
        pa[l] = loc[i] * inv;
        run += loc[i];
        ps[l + 1] = run * inv;
    }
}

// ------------------------- attention scores -------------------------
// scores[b,h,p,l] = (q[b,l,h,:] . k[b,p,h,:]) / 8
__global__ void __launch_bounds__(256) scores_kernel(
    const float* __restrict__ q, const float* __restrict__ k,
    float* __restrict__ scores)
{
    const int lt = blockIdx.x;  // L/64
    const int h = blockIdx.y, b = blockIdx.z;
    const int l0 = lt * 64;
    const int tid = threadIdx.x;
    __shared__ float sk[64][65];  // [d][p]
    __shared__ float sq[64][65];  // [d][l]

#pragma unroll
    for (int it = 0; it < 4; ++it) {
        int f = tid + it * 256;
        int p = f / 16, d4 = f % 16;
        float4 v = *(const float4*)&k[((long)(b * PP + p)) * HD + h * 64 + d4 * 4];
        sk[d4 * 4 + 0][p] = v.x; sk[d4 * 4 + 1][p] = v.y;
        sk[d4 * 4 + 2][p] = v.z; sk[d4 * 4 + 3][p] = v.w;
    }
#pragma unroll
    for (int it = 0; it < 4; ++it) {
        int f = tid + it * 256;
        int l = f / 16, d4 = f % 16;
        float4 v = *(const float4*)&q[((long)(b * LL + l0 + l)) * HD + h * 64 + d4 * 4];
        sq[d4 * 4 + 0][l] = v.x; sq[d4 * 4 + 1][l] = v.y;
        sq[d4 * 4 + 2][l] = v.z; sq[d4 * 4 + 3][l] = v.w;
    }
    __syncthreads();

    const int ty = tid / 16;  // p group
    const int tx = tid % 16;  // l group
    float acc[4][4] = {};
#pragma unroll
    for (int d = 0; d < 64; d++) {
        float a[4], bb[4];
#pragma unroll
        for (int i = 0; i < 4; i++) a[i] = sk[d][ty * 4 + i];
#pragma unroll
        for (int j = 0; j < 4; j++) bb[j] = sq[d][tx * 4 + j];
#pragma unroll
        for (int i = 0; i < 4; i++)
#pragma unroll
            for (int j = 0; j < 4; j++) acc[i][j] += a[i] * bb[j];
    }
#pragma unroll
    for (int i = 0; i < 4; i++) {
        int p = ty * 4 + i;
#pragma unroll
        for (int j = 0; j < 4; j++) {
            int l = tx * 4 + j;
            scores[(((long)(b * HH + h)) * PP + p) * LL + l0 + l] = acc[i][j] * 0.125f;
        }
    }
}

// ------------------------- relative-position bias -------------------------
// scores[b,h,p,l] = scores*Kb + bb where Kb/bb come from 15 banded sums of pA.
__global__ void __launch_bounds__(256) relbias_kernel(
    const float* __restrict__ PS, const float* __restrict__ pAT,
    const float* __restrict__ embK, const float* __restrict__ embB,
    float* __restrict__ scores)
{
    const int l = blockIdx.x * 256 + threadIdx.x;
    const int p = blockIdx.y, b = blockIdx.z;
    __shared__ float sK[120], sB[120];
    if (threadIdx.x < 120) {
        sK[threadIdx.x] = embK[threadIdx.x];
        sB[threadIdx.x] = embB[threadIdx.x];
    }
    __syncthreads();

    const float* ps = PS + ((long)(b * PP + p)) * (LL + 1);
    float S[15];
    S[0] = pAT[((long)(b * PP + p)) * LL + l];
#pragma unroll
    for (int t = 1; t < 15; t++) {
        int lo = c_lo[t], hi = c_hi[t];
        float s = 0.f;
        int a1 = l - lo;
        if (a1 >= 0) {
            int a0 = l - hi; if (a0 < 0) a0 = 0;
            s += ps[a1 + 1] - ps[a0];
        }
        int b0 = l + lo;
        if (b0 < LL) {
            int b1 = l + hi; if (b1 > LL - 1) b1 = LL - 1;
            s += ps[b1 + 1] - ps[b0];
        }
        S[t] = s;
    }
#pragma unroll
    for (int h = 0; h < HH; h++) {
        float kb = 0.f, bb = 0.f;
#pragma unroll
        for (int t = 0; t < 15; t++) {
            kb += S[t] * sK[t * HH + h];
            bb += S[t] * sB[t * HH + h];
        }
        long idx = (((long)(b * HH + h)) * PP + p) * LL + l;
        scores[idx] = scores[idx] * kb + bb;
    }
}

// ------------------------- softmax over P (=64) -------------------------
__global__ void __launch_bounds__(256) softmaxP_kernel(float* __restrict__ scores)
{
    const long l = blockIdx.x * 256 + threadIdx.x;
    const int bh = blockIdx.y;
    float* base = scores + (long)bh * PP * LL + l;
    float v[PP];
    float mx = -3.0e38f;
#pragma unroll
    for (int p = 0; p < PP; p++) {
        v[p] = base[(long)p * LL];
        mx = fmaxf(mx, v[p]);
    }
    float s = 0.f;
#pragma unroll
    for (int p = 0; p < PP; p++) {
        v[p] = expf(v[p] - mx);
        s += v[p];
    }
    float inv = 1.0f / s;
#pragma unroll
    for (int p = 0; p < PP; p++) base[(long)p * LL] = v[p] * inv;
}

// ------------------------- z = alpha @ v -------------------------
// z[b, l, h*64+d] = sum_p alpha[b,h,p,l] * v[b,p,h*64+d]
__global__ void __launch_bounds__(256) zhead_kernel(
    const float* __restrict__ alpha, const float* __restrict__ v,
    float* __restrict__ z)
{
    const int lt = blockIdx.x;
    const int h = blockIdx.y, b = blockIdx.z;
    const int l0 = lt * 64;
    const int tid = threadIdx.x;
    __shared__ float sa[64][64];  // [p][l]
    __shared__ float sv[64][64];  // [p][d]

#pragma unroll
    for (int it = 0; it < 4; ++it) {
        int f = tid + it * 256;
        int p = f / 16, l4 = f % 16;
        *(float4*)&sa[p][l4 * 4] =
            *(const float4*)&alpha[(((long)(b * HH + h)) * PP + p) * LL + l0 + l4 * 4];
    }
#pragma unroll
    for (int it = 0; it < 4; ++it) {
        int f = tid + it * 256;
        int p = f / 16, d4 = f % 16;
        *(float4*)&sv[p][d4 * 4] =
            *(const float4*)&v[((long)(b * PP + p)) * HD + h * 64 + d4 * 4];
    }
    __syncthreads();

    const int ty = tid / 16;  // l group
    const int tx = tid % 16;  // d group
    float acc[4][4] = {};
#pragma unroll
    for (int p = 0; p < 64; p++) {
        float a[4], bb[4];
#pragma unroll
        for (int i = 0; i < 4; i++) a[i] = sa[p][ty * 4 + i];
#pragma unroll
        for (int j = 0; j < 4; j++) bb[j] = sv[p][tx * 4 + j];
#pragma unroll
        for (int i = 0; i < 4; i++)
#pragma unroll
            for (int j = 0; j < 4; j++) acc[i][j] += a[i] * bb[j];
    }
#pragma unroll
    for (int i = 0; i < 4; i++) {
        int l = l0 + ty * 4 + i;
#pragma unroll
        for (int j = 0; j < 4; j++) {
            z[((long)(b * LL + l)) * HD + h * 64 + tx * 4 + j] = acc[i][j];
        }
    }
}

// ------------------------- layernorm (row of 512) -------------------------
__global__ void __launch_bounds__(256) ln_kernel(
    const float* __restrict__ x, const float* __restrict__ g,
    const float* __restrict__ b, float* __restrict__ out)
{
    const int row = blockIdx.x;
    const int tid = threadIdx.x;
    __shared__ float red[256];
    float2 v = ((const float2*)(x + (long)row * CC))[tid];

    red[tid] = v.x + v.y;
    __syncthreads();
    for (int s = 128; s > 0; s >>= 1) {
        if (tid < s) red[tid] += red[tid + s];
        __syncthreads();
    }
    float mean = red[0] * (1.0f / CC);
    __syncthreads();

    float dx = v.x - mean, dy = v.y - mean;
    red[tid] = dx * dx + dy * dy;
    __syncthreads();
    for (int s = 128; s > 0; s >>= 1) {
        if (tid < s) red[tid] += red[tid + s];
        __syncthreads();
    }
    float var = red[0] * (1.0f / CC);
    float rstd = rsqrtf(var + 1e-5f);

    int c = tid * 2;
    float2 o;
    o.x = dx * rstd * g[c] + b[c];
    o.y = dy * rstd * g[c + 1] + b[c + 1];
    ((float2*)(out + (long)row * CC))[tid] = o;
}

// ------------------------- host launch -------------------------
extern "C" void kernel_launch(void* const* d_in, const int* in_sizes, int n_in,
                              void* d_out, int out_size)
{
    const float* qx = (const float*)d_in[0];
    const float* kx = (const float*)d_in[1];
    const float* vx = (const float*)d_in[2];
    const int* maskPAD = (const int*)d_in[3];
    const float* Wp = (const float*)d_in[4];
    const float* bp = (const float*)d_in[5];
    const float* WQ = (const float*)d_in[6];
    const float* bQ = (const float*)d_in[7];
    const float* WK = (const float*)d_in[8];
    const float* bK = (const float*)d_in[9];
    const float* WV = (const float*)d_in[10];
    const float* bV = (const float*)d_in[11];
    const float* WO = (const float*)d_in[12];
    const float* bO = (const float*)d_in[13];
    const float* embK = (const float*)d_in[14];
    const float* embB = (const float*)d_in[15];
    const float* ln1_g = (const float*)d_in[16];
    const float* ln1_b = (const float*)d_in[17];
    const float* ln2_g = (const float*)d_in[18];
    const float* ln2_b = (const float*)d_in[19];
    const float* W1 = (const float*)d_in[20];
    const float* b1 = (const float*)d_in[21];
    const float* W2 = (const float*)d_in[22];
    const float* b2 = (const float*)d_in[23];
    float* out = (float*)d_out;

    float *d_pscore, *d_pAT, *d_PS, *d_kxp, *d_vxp, *d_q, *d_k, *d_v;
    float *d_scores, *d_z, *d_y1, *d_z1, *d_h1, *d_y2;
    cudaGetSymbolAddress((void**)&d_pscore, g_pscore);
    cudaGetSymbolAddress((void**)&d_pAT, g_pAT);
    cudaGetSymbolAddress((void**)&d_PS, g_PS);
    cudaGetSymbolAddress((void**)&d_kxp, g_kxp);
    cudaGetSymbolAddress((void**)&d_vxp, g_vxp);
    cudaGetSymbolAddress((void**)&d_q, g_q);
    cudaGetSymbolAddress((void**)&d_k, g_k);
    cudaGetSymbolAddress((void**)&d_v, g_v);
    cudaGetSymbolAddress((void**)&d_scores, g_scores);
    cudaGetSymbolAddress((void**)&d_z, g_z);
    cudaGetSymbolAddress((void**)&d_y1, g_y1);
    cudaGetSymbolAddress((void**)&d_z1, g_z1);
    cudaGetSymbolAddress((void**)&d_h1, g_h1);
    cudaGetSymbolAddress((void**)&d_y2, g_y2);

    const int M = BB * LL;  // 16384

    // 1) pScore = vx @ Wp + bp           (16384 x 64, K=512)
    sgemm<128, 64, 16, 8, 4, 1><<<dim3(1, M / 128, 1), 256>>>(
        vx, Wp, bp, nullptr, d_pscore, M, PP, CC, 0, 0, 0);

    // 2) softmax over L + prefix scan
    softmax_scan_kernel<<<dim3(PP, BB), 256>>>(d_pscore, maskPAD, d_pAT, d_PS);

    // 3,4) kxp/vxp = pAT @ {kx,vx}       (batched: 64 x 512, K=1024)
    sgemm<64, 64, 16, 4, 4, 0><<<dim3(CC / 64, 1, BB), 256>>>(
        d_pAT, kx, nullptr, nullptr, d_kxp, PP, CC, LL,
        (long)PP * LL, (long)LL * CC, (long)PP * CC);
    sgemm<64, 64, 16, 4, 4, 0><<<dim3(CC / 64, 1, BB), 256>>>(
        d_pAT, vx, nullptr, nullptr, d_vxp, PP, CC, LL,
        (long)PP * LL, (long)LL * CC, (long)PP * CC);

    // 5) q = qx @ WQ + bQ                (16384 x 512, K=512)
    sgemm<128, 128, 16, 8, 8, 1><<<dim3(HD / 128, M / 128, 1), 256>>>(
        qx, WQ, bQ, nullptr, d_q, M, HD, CC, 0, 0, 0);

    // 6,7) k/v = kxp/vxp @ WK/WV + b     (1024 x 512, K=512)
    sgemm<128, 128, 16, 8, 8, 1><<<dim3(HD / 128, (BB * PP) / 128, 1), 256>>>(
        d_kxp, WK, bK, nullptr, d_k, BB * PP, HD, CC, 0, 0, 0);
    sgemm<128, 128, 16, 8, 8, 1><<<dim3(HD / 128, (BB * PP) / 128, 1), 256>>>(
        d_vxp, WV, bV, nullptr, d_v, BB * PP, HD, CC, 0, 0, 0);

    // 8) scores (B,H,P,L)
    scores_kernel<<<dim3(LL / 64, HH, BB), 256>>>(d_q, d_k, d_scores);

    // 9) relative-position bias via banded prefix sums
    relbias_kernel<<<dim3(LL / 256, PP, BB), 256>>>(d_PS, d_pAT, embK, embB, d_scores);

    // 10) softmax over P
    softmaxP_kernel<<<dim3(LL / 256, BB * HH), 256>>>(d_scores);

    // 11) z = alpha @ v
    zhead_kernel<<<dim3(LL / 64, HH, BB), 256>>>(d_scores, d_v, d_z);

    // 12) y1 = z @ WO + bO + vx
    sgemm<128, 128, 16, 8, 8, 2><<<dim3(CC / 128, M / 128, 1), 256>>>(
        d_z, WO, bO, vx, d_y1, M, CC, HD, 0, 0, 0);

    // 13) z1 = LN1(y1)
    ln_kernel<<<M, 256>>>(d_y1, ln1_g, ln1_b, d_z1);

    // 14) h1 = gelu(z1 @ W1 + b1)        (16384 x 2048, K=512)
    sgemm<128, 128, 16, 8, 8, 3><<<dim3(FF / 128, M / 128, 1), 256>>>(
        d_z1, W1, b1, nullptr, d_h1, M, FF, CC, 0, 0, 0);

    // 15) y2 = h1 @ W2 + b2 + z1         (16384 x 512, K=2048)
    sgemm<128, 128, 16, 8, 8, 2><<<dim3(CC / 128, M / 128, 1), 256>>>(
        d_h1, W2, b2, d_z1, d_y2, M, CC, FF, 0, 0, 0);

    // 16) out = LN2(y2)
    ln_kernel<<<M, 256>>>(d_y2, ln2_g, ln2_b, out);
}

// round 14
// speedup vs baseline: 1.0040x; 1.0009x over previous
#include <cuda_runtime.h>
#include <math.h>

#define BB 16
#define LL 1024
#define CC 512
#define PP 64
#define HH 8
#define DKK 64
#define HD 512
#define FF 2048

// ------------------------- device scratch -------------------------
__device__ float g_pscore[BB * LL * PP];           // (B,L,P)
__device__ float g_pAT[BB * PP * LL];              // (B,P,L)
__device__ float g_PS[BB * PP * (LL + 1)];         // prefix sums over m
__device__ float g_kxp[BB * PP * CC];
__device__ float g_vxp[BB * PP * CC];
__device__ float g_q[BB * LL * HD];
__device__ float g_k[BB * PP * HD];
__device__ float g_v[BB * PP * HD];
__device__ float g_scores[BB * HH * PP * LL];      // (B,H,P,L)
__device__ float g_z[BB * LL * HD];
__device__ float g_y1[BB * LL * CC];
__device__ float g_z1[BB * LL * CC];
__device__ float g_h1[(long)BB * LL * FF];
__device__ float g_y2[BB * LL * CC];

// relative position bucket distance ranges (t=0..14)
__constant__ int c_lo[15] = {0,1,2,3,4,5,6,7, 9,11,15,23,39, 71,135};
__constant__ int c_hi[15] = {0,1,2,3,4,5,6,8,10,14,22,38,70,134,1023};

__device__ __forceinline__ float gelu_exact(float x) {
    return 0.5f * x * (1.0f + erff(x * 0.70710678118654752f));
}

// ------------------------- generic SGEMM -------------------------
// C[M,N] = A[M,K] @ W[K,N] (+bias)(+res)(gelu). Row-major. Shapes must be
// multiples of the tile sizes (they are, for every call below).
// EPI: 0 = none, 1 = +bias, 2 = +bias+res, 3 = +bias then gelu
template <int BM, int BN, int BK, int TM, int TN, int EPI>
__global__ void __launch_bounds__(256) sgemm(
    const float* __restrict__ A, const float* __restrict__ W,
    const float* __restrict__ bias, const float* __restrict__ res,
    float* __restrict__ C, int M, int N, int K,
    long sA, long sB, long sC)
{
    __shared__ float As[BK][BM + 4];
    __shared__ float Bs[BK][BN];
    const int tid = threadIdx.x;
    const int bz = blockIdx.z;
    A += (long)bz * sA;
    W += (long)bz * sB;
    C += (long)bz * sC;
    const int m0 = blockIdx.y * BM;
    const int n0 = blockIdx.x * BN;

    const int tx = tid % (BN / TN);
    const int ty = tid / (BN / TN);

    float acc[TM][TN];
#pragma unroll
    for (int i = 0; i < TM; i++)
#pragma unroll
        for (int j = 0; j < TN; j++) acc[i][j] = 0.f;

    for (int k0 = 0; k0 < K; k0 += BK) {
        // load A tile (BM x BK), store transposed
#pragma unroll
        for (int it = 0; it < BM * BK / 1024; ++it) {
            int f = tid + it * 256;
            int row = f / (BK / 4);
            int c4 = f % (BK / 4);
            float4 v = *(const float4*)&A[(long)(m0 + row) * K + k0 + c4 * 4];
            As[c4 * 4 + 0][row] = v.x;
            As[c4 * 4 + 1][row] = v.y;
            As[c4 * 4 + 2][row] = v.z;
            As[c4 * 4 + 3][row] = v.w;
        }
        // load B tile (BK x BN)
#pragma unroll
        for (int it = 0; it < BK * BN / 1024; ++it) {
            int f = tid + it * 256;
            int row = f / (BN / 4);
            int c4 = f % (BN / 4);
            *(float4*)&Bs[row][c4 * 4] =
                *(const float4*)&W[(long)(k0 + row) * N + n0 + c4 * 4];
        }
        __syncthreads();
#pragma unroll
        for (int kk = 0; kk < BK; ++kk) {
            float a[TM], bfrag[TN];
#pragma unroll
            for (int i = 0; i < TM / 4; i++)
                ((float4*)a)[i] = *(const float4*)&As[kk][ty * TM + i * 4];
#pragma unroll
            for (int j = 0; j < TN / 4; j++)
                ((float4*)bfrag)[j] = *(const float4*)&Bs[kk][tx * TN + j * 4];
#pragma unroll
            for (int i = 0; i < TM; i++)
#pragma unroll
                for (int j = 0; j < TN; j++) acc[i][j] += a[i] * bfrag[j];
        }
        __syncthreads();
    }

#pragma unroll
    for (int i = 0; i < TM; i++) {
        int row = m0 + ty * TM + i;
#pragma unroll
        for (int j = 0; j < TN; j++) {
            int col = n0 + tx * TN + j;
            float v = acc[i][j];
            if (EPI >= 1) v += bias[col];
            long idx = (long)row * N + col;
            if (EPI == 2) v += res[idx];
            if (EPI == 3) v = gelu_exact(v);
            C[idx] = v;
        }
    }
}

// --------------- pseudo-token softmax over L + prefix scan ---------------
// one block per (p, b). Produces pAT (B,P,L) and PS (B,P,L+1).
__global__ void __launch_bounds__(256) softmax_scan_kernel(
    const float* __restrict__ pscore, const int* __restrict__ maskPAD,
    float* __restrict__ pAT, float* __restrict__ PS)
{
    const int p = blockIdx.x, b = blockIdx.y;
    const int tid = threadIdx.x;
    __shared__ float red[256];

    float loc[4];
    float mx = -3.0e38f;
#pragma unroll
    for (int i = 0; i < 4; i++) {
        int l = tid * 4 + i;
        float v = pscore[((long)(b * LL + l)) * PP + p];
        if (maskPAD[(long)b * LL * LL + l] == 0) v = -32768.0f;
        loc[i] = v;
        mx = fmaxf(mx, v);
    }
    red[tid] = mx;
    __syncthreads();
    for (int s = 128; s > 0; s >>= 1) {
        if (tid < s) red[tid] = fmaxf(red[tid], red[tid + s]);
        __syncthreads();
    }
    mx = red[0];
    __syncthreads();

    float tsum = 0.f;
#pragma unroll
    for (int i = 0; i < 4; i++) {
        loc[i] = expf(loc[i] - mx);
        tsum += loc[i];
    }
    red[tid] = tsum;
    __syncthreads();
    // Hillis-Steele inclusive scan over thread sums
    for (int off = 1; off < 256; off <<= 1) {
        float t = (tid >= off) ? red[tid - off] : 0.f;
        __syncthreads();
        red[tid] += t;
        __syncthreads();
    }
    float total = red[255];
    float excl = red[tid] - tsum;
    float inv = 1.0f / total;

    float* pa = pAT + ((long)(b * PP + p)) * LL;
    float* ps = PS + ((long)(b * PP + p)) * (LL + 1);
    if (tid == 0) ps[0] = 0.f;
    float run = excl;
#pragma unroll
    for (int i = 0; i < 4; i++) {
        int l = tid * 4 + i;
        pa[l] = loc[i] * inv;
        run += loc[i];
        ps[l + 1] = run * inv;
    }
}

// ------------------------- attention scores -------------------------
// scores[b,h,p,l] = (q[b,l,h,:] . k[b,p,h,:]) / 8
__global__ void __launch_bounds__(256) scores_kernel(
    const float* __restrict__ q, const float* __restrict__ k,
    float* __restrict__ scores)
{
    const int lt = blockIdx.x;  // L/64
    const int h = blockIdx.y, b = blockIdx.z;
    const int l0 = lt * 64;
    const int tid = threadIdx.x;
    __shared__ float sk[64][65];  // [d][p]
    __shared__ float sq[64][65];  // [d][l]

#pragma unroll
    for (int it = 0; it < 4; ++it) {
        int f = tid + it * 256;
        int p = f / 16, d4 = f % 16;
        float4 v = *(const float4*)&k[((long)(b * PP + p)) * HD + h * 64 + d4 * 4];
        sk[d4 * 4 + 0][p] = v.x; sk[d4 * 4 + 1][p] = v.y;
        sk[d4 * 4 + 2][p] = v.z; sk[d4 * 4 + 3][p] = v.w;
    }
#pragma unroll
    for (int it = 0; it < 4; ++it) {
        int f = tid + it * 256;
        int l = f / 16, d4 = f % 16;
        float4 v = *(const float4*)&q[((long)(b * LL + l0 + l)) * HD + h * 64 + d4 * 4];
        sq[d4 * 4 + 0][l] = v.x; sq[d4 * 4 + 1][l] = v.y;
        sq[d4 * 4 + 2][l] = v.z; sq[d4 * 4 + 3][l] = v.w;
    }
    __syncthreads();

    const int ty = tid / 16;  // p group
    const int tx = tid % 16;  // l group
    float acc[4][4] = {};
#pragma unroll
    for (int d = 0; d < 64; d++) {
        float a[4], bb[4];
#pragma unroll
        for (int i = 0; i < 4; i++) a[i] = sk[d][ty * 4 + i];
#pragma unroll
        for (int j = 0; j < 4; j++) bb[j] = sq[d][tx * 4 + j];
#pragma unroll
        for (int i = 0; i < 4; i++)
#pragma unroll
            for (int j = 0; j < 4; j++) acc[i][j] += a[i] * bb[j];
    }
#pragma unroll
    for (int i = 0; i < 4; i++) {
        int p = ty * 4 + i;
#pragma unroll
        for (int j = 0; j < 4; j++) {
            int l = tx * 4 + j;
            scores[(((long)(b * HH + h)) * PP + p) * LL + l0 + l] = acc[i][j] * 0.125f;
        }
    }
}

// ------------------------- relative-position bias -------------------------
// scores[b,h,p,l] = scores*Kb + bb where Kb/bb come from 15 banded sums of pA.
__global__ void __launch_bounds__(256) relbias_kernel(
    const float* __restrict__ PS, const float* __restrict__ pAT,
    const float* __restrict__ embK, const float* __restrict__ embB,
    float* __restrict__ scores)
{
    const int l = blockIdx.x * 256 + threadIdx.x;
    const int p = blockIdx.y, b = blockIdx.z;
    __shared__ float sK[120], sB[120];
    if (threadIdx.x < 120) {
        sK[threadIdx.x] = embK[threadIdx.x];
        sB[threadIdx.x] = embB[threadIdx.x];
    }
    __syncthreads();

    const float* ps = PS + ((long)(b * PP + p)) * (LL + 1);
    float S[15];
    S[0] = pAT[((long)(b * PP + p)) * LL + l];
#pragma unroll
    for (int t = 1; t < 15; t++) {
        int lo = c_lo[t], hi = c_hi[t];
        float s = 0.f;
        int a1 = l - lo;
        if (a1 >= 0) {
            int a0 = l - hi; if (a0 < 0) a0 = 0;
            s += ps[a1 + 1] - ps[a0];
        }
        int b0 = l + lo;
        if (b0 < LL) {
            int b1 = l + hi; if (b1 > LL - 1) b1 = LL - 1;
            s += ps[b1 + 1] - ps[b0];
        }
        S[t] = s;
    }
#pragma unroll
    for (int h = 0; h < HH; h++) {
        float kb = 0.f, bb = 0.f;
#pragma unroll
        for (int t = 0; t < 15; t++) {
            kb += S[t] * sK[t * HH + h];
            bb += S[t] * sB[t * HH + h];
        }
        long idx = (((long)(b * HH + h)) * PP + p) * LL + l;
        scores[idx] = scores[idx] * kb + bb;
    }
}

// ------------------------- softmax over P (=64) -------------------------
__global__ void __launch_bounds__(256) softmaxP_kernel(float* __restrict__ scores)
{
    const long l = blockIdx.x * 256 + threadIdx.x;
    const int bh = blockIdx.y;
    float* base = scores + (long)bh * PP * LL + l;
    float v[PP];
    float mx = -3.0e38f;
#pragma unroll
    for (int p = 0; p < PP; p++) {
        v[p] = base[(long)p * LL];
        mx = fmaxf(mx, v[p]);
    }
    float s = 0.f;
#pragma unroll
    for (int p = 0; p < PP; p++) {
        v[p] = expf(v[p] - mx);
        s += v[p];
    }
    float inv = 1.0f / s;
#pragma unroll
    for (int p = 0; p < PP; p++) base[(long)p * LL] = v[p] * inv;
}

// ------------------------- z = alpha @ v -------------------------
// z[b, l, h*64+d] = sum_p alpha[b,h,p,l] * v[b,p,h*64+d]
__global__ void __launch_bounds__(256) zhead_kernel(
    const float* __restrict__ alpha, const float* __restrict__ v,
    float* __restrict__ z)
{
    const int lt = blockIdx.x;
    const int h = blockIdx.y, b = blockIdx.z;
    const int l0 = lt * 64;
    const int tid = threadIdx.x;
    __shared__ float sa[64][64];  // [p][l]
    __shared__ float sv[64][64];  // [p][d]

#pragma unroll
    for (int it = 0; it < 4; ++it) {
        int f = tid + it * 256;
        int p = f / 16, l4 = f % 16;
        *(float4*)&sa[p][l4 * 4] =
            *(const float4*)&alpha[(((long)(b * HH + h)) * PP + p) * LL + l0 + l4 * 4];
    }
#pragma unroll
    for (int it = 0; it < 4; ++it) {
        int f = tid + it * 256;
        int p = f / 16, d4 = f % 16;
        *(float4*)&sv[p][d4 * 4] =
            *(const float4*)&v[((long)(b * PP + p)) * HD + h * 64 + d4 * 4];
    }
    __syncthreads();

    const int ty = tid / 16;  // l group
    const int tx = tid % 16;  // d group
    float acc[4][4] = {};
#pragma unroll
    for (int p = 0; p < 64; p++) {
        float a[4], bb[4];
#pragma unroll
        for (int i = 0; i < 4; i++) a[i] = sa[p][ty * 4 + i];
#pragma unroll
        for (int j = 0; j < 4; j++) bb[j] = sv[p][tx * 4 + j];
#pragma unroll
        for (int i = 0; i < 4; i++)
#pragma unroll
            for (int j = 0; j < 4; j++) acc[i][j] += a[i] * bb[j];
    }
#pragma unroll
    for (int i = 0; i < 4; i++) {
        int l = l0 + ty * 4 + i;
#pragma unroll
        for (int j = 0; j < 4; j++) {
            z[((long)(b * LL + l)) * HD + h * 64 + tx * 4 + j] = acc[i][j];
        }
    }
}

// ------------------------- layernorm (row of 512) -------------------------
__global__ void __launch_bounds__(256) ln_kernel(
    const float* __restrict__ x, const float* __restrict__ g,
    const float* __restrict__ b, float* __restrict__ out)
{
    const int row = blockIdx.x;
    const int tid = threadIdx.x;
    __shared__ float red[256];
    float2 v = ((const float2*)(x + (long)row * CC))[tid];

    red[tid] = v.x + v.y;
    __syncthreads();
    for (int s = 128; s > 0; s >>= 1) {
        if (tid < s) red[tid] += red[tid + s];
        __syncthreads();
    }
    float mean = red[0] * (1.0f / CC);
    __syncthreads();

    float dx = v.x - mean, dy = v.y - mean;
    red[tid] = dx * dx + dy * dy;
    __syncthreads();
    for (int s = 128; s > 0; s >>= 1) {
        if (tid < s) red[tid] += red[tid + s];
        __syncthreads();
    }
    float var = red[0] * (1.0f / CC);
    float rstd = rsqrtf(var + 1e-5f);

    int c = tid * 2;
    float2 o;
    o.x = dx * rstd * g[c] + b[c];
    o.y = dy * rstd * g[c + 1] + b[c + 1];
    ((float2*)(out + (long)row * CC))[tid] = o;
}

// ------------------------- host launch -------------------------
extern "C" void kernel_launch(void* const* d_in, const int* in_sizes, int n_in,
                              void* d_out, int out_size)
{
    const float* qx = (const float*)d_in[0];
    const float* kx = (const float*)d_in[1];
    const float* vx = (const float*)d_in[2];
    const int* maskPAD = (const int*)d_in[3];
    const float* Wp = (const float*)d_in[4];
    const float* bp = (const float*)d_in[5];
    const float* WQ = (const float*)d_in[6];
    const float* bQ = (const float*)d_in[7];
    const float* WK = (const float*)d_in[8];
    const float* bK = (const float*)d_in[9];
    const float* WV = (const float*)d_in[10];
    const float* bV = (const float*)d_in[11];
    const float* WO = (const float*)d_in[12];
    const float* bO = (const float*)d_in[13];
    const float* embK = (const float*)d_in[14];
    const float* embB = (const float*)d_in[15];
    const float* ln1_g = (const float*)d_in[16];
    const float* ln1_b = (const float*)d_in[17];
    const float* ln2_g = (const float*)d_in[18];
    const float* ln2_b = (const float*)d_in[19];
    const float* W1 = (const float*)d_in[20];
    const float* b1 = (const float*)d_in[21];
    const float* W2 = (const float*)d_in[22];
    const float* b2 = (const float*)d_in[23];
    float* out = (float*)d_out;

    float *d_pscore, *d_pAT, *d_PS, *d_kxp, *d_vxp, *d_q, *d_k, *d_v;
    float *d_scores, *d_z, *d_y1, *d_z1, *d_h1, *d_y2;
    cudaGetSymbolAddress((void**)&d_pscore, g_pscore);
    cudaGetSymbolAddress((void**)&d_pAT, g_pAT);
    cudaGetSymbolAddress((void**)&d_PS, g_PS);
    cudaGetSymbolAddress((void**)&d_kxp, g_kxp);
    cudaGetSymbolAddress((void**)&d_vxp, g_vxp);
    cudaGetSymbolAddress((void**)&d_q, g_q);
    cudaGetSymbolAddress((void**)&d_k, g_k);
    cudaGetSymbolAddress((void**)&d_v, g_v);
    cudaGetSymbolAddress((void**)&d_scores, g_scores);
    cudaGetSymbolAddress((void**)&d_z, g_z);
    cudaGetSymbolAddress((void**)&d_y1, g_y1);
    cudaGetSymbolAddress((void**)&d_z1, g_z1);
    cudaGetSymbolAddress((void**)&d_h1, g_h1);
    cudaGetSymbolAddress((void**)&d_y2, g_y2);

    const int M = BB * LL;  // 16384

    // 1) pScore = vx @ Wp + bp           (16384 x 64, K=512)
    sgemm<128, 64, 16, 8, 4, 1><<<dim3(1, M / 128, 1), 256>>>(
        vx, Wp, bp, nullptr, d_pscore, M, PP, CC, 0, 0, 0);

    // 2) softmax over L + prefix scan
    softmax_scan_kernel<<<dim3(PP, BB), 256>>>(d_pscore, maskPAD, d_pAT, d_PS);

    // 3,4) kxp/vxp = pAT @ {kx,vx}       (batched: 64 x 512, K=1024)
    sgemm<64, 64, 16, 4, 4, 0><<<dim3(CC / 64, 1, BB), 256>>>(
        d_pAT, kx, nullptr, nullptr, d_kxp, PP, CC, LL,
        (long)PP * LL, (long)LL * CC, (long)PP * CC);
    sgemm<64, 64, 16, 4, 4, 0><<<dim3(CC / 64, 1, BB), 256>>>(
        d_pAT, vx, nullptr, nullptr, d_vxp, PP, CC, LL,
        (long)PP * LL, (long)LL * CC, (long)PP * CC);

    // 5) q = qx @ WQ + bQ                (16384 x 512, K=512)
    sgemm<128, 128, 16, 8, 8, 1><<<dim3(HD / 128, M / 128, 1), 256>>>(
        qx, WQ, bQ, nullptr, d_q, M, HD, CC, 0, 0, 0);

    // 6,7) k/v = kxp/vxp @ WK/WV + b     (1024 x 512, K=512)
    sgemm<128, 128, 16, 8, 8, 1><<<dim3(HD / 128, (BB * PP) / 128, 1), 256>>>(
        d_kxp, WK, bK, nullptr, d_k, BB * PP, HD, CC, 0, 0, 0);
    sgemm<128, 128, 16, 8, 8, 1><<<dim3(HD / 128, (BB * PP) / 128, 1), 256>>>(
        d_vxp, WV, bV, nullptr, d_v, BB * PP, HD, CC, 0, 0, 0);

    // 8) scores (B,H,P,L)
    scores_kernel<<<dim3(LL / 64, HH, BB), 256>>>(d_q, d_k, d_scores);

    // 9) relative-position bias via banded prefix sums
    relbias_kernel<<<dim3(LL / 256, PP, BB), 256>>>(d_PS, d_pAT, embK, embB, d_scores);

    // 10) softmax over P
    softmaxP_kernel<<<dim3(LL / 256, BB * HH), 256>>>(d_scores);

    // 11) z = alpha @ v
    zhead_kernel<<<dim3(LL / 64, HH, BB), 256>>>(d_scores, d_v, d_z);

    // 12) y1 = z @ WO + bO + vx
    sgemm<128, 128, 16, 8, 8, 2><<<dim3(CC / 128, M / 128, 1), 256>>>(
        d_z, WO, bO, vx, d_y1, M, CC, HD, 0, 0, 0);

    // 13) z1 = LN1(y1)
    ln_kernel<<<M, 256>>>(d_y1, ln1_g, ln1_b, d_z1);

    // 14) h1 = gelu(z1 @ W1 + b1)        (16384 x 2048, K=512)
    sgemm<128, 128, 16, 8, 8, 3><<<dim3(FF / 128, M / 128, 1), 256>>>(
        d_z1, W1, b1, nullptr, d_h1, M, FF, CC, 0, 0, 0);

    // 15) y2 = h1 @ W2 + b2 + z1         (16384 x 512, K=2048)
    sgemm<128, 128, 16, 8, 8, 2><<<dim3(CC / 128, M / 128, 1), 256>>>(
        d_h1, W2, b2, d_z1, d_y2, M, CC, FF, 0, 0, 0);

    // 16) out = LN2(y2)
    ln_kernel<<<M, 256>>>(d_y2, ln2_g, ln2_b, out);
}

// round 17
// speedup vs baseline: 1.0045x; 1.0005x over previous
#include <cuda_runtime.h>
#include <math.h>

#define BB 16
#define LL 1024
#define CC 512
#define PP 64
#define HH 8
#define DKK 64
#define HD 512
#define FF 2048

// ------------------------- device scratch -------------------------
__device__ float g_pscore[BB * LL * PP];           // (B,L,P)
__device__ float g_pAT[BB * PP * LL];              // (B,P,L)
__device__ float g_PS[BB * PP * (LL + 1)];         // prefix sums over m
__device__ float g_kxp[BB * PP * CC];
__device__ float g_vxp[BB * PP * CC];
__device__ float g_q[BB * LL * HD];
__device__ float g_k[BB * PP * HD];
__device__ float g_v[BB * PP * HD];
__device__ float g_scores[BB * HH * PP * LL];      // (B,H,P,L)
__device__ float g_z[BB * LL * HD];
__device__ float g_y1[BB * LL * CC];
__device__ float g_z1[BB * LL * CC];
__device__ float g_h1[(long)BB * LL * FF];
__device__ float g_y2[BB * LL * CC];

// relative position bucket distance ranges (t=0..14)
__constant__ int c_lo[15] = {0,1,2,3,4,5,6,7, 9,11,15,23,39, 71,135};
__constant__ int c_hi[15] = {0,1,2,3,4,5,6,8,10,14,22,38,70,134,1023};

__device__ __forceinline__ float gelu_exact(float x) {
    return 0.5f * x * (1.0f + erff(x * 0.70710678118654752f));
}

// ------------------------- generic SGEMM -------------------------
// C[M,N] = A[M,K] @ W[K,N] (+bias)(+res)(gelu). Row-major. Shapes must be
// multiples of the tile sizes (they are, for every call below).
// EPI: 0 = none, 1 = +bias, 2 = +bias+res, 3 = +bias then gelu
template <int BM, int BN, int BK, int TM, int TN, int EPI>
__global__ void __launch_bounds__(256) sgemm(
    const float* __restrict__ A, const float* __restrict__ W,
    const float* __restrict__ bias, const float* __restrict__ res,
    float* __restrict__ C, int M, int N, int K,
    long sA, long sB, long sC)
{
    __shared__ float As[BK][BM + 4];
    __shared__ float Bs[BK][BN];
    const int tid = threadIdx.x;
    const int bz = blockIdx.z;
    A += (long)bz * sA;
    W += (long)bz * sB;
    C += (long)bz * sC;
    const int m0 = blockIdx.y * BM;
    const int n0 = blockIdx.x * BN;

    const int tx = tid % (BN / TN);
    const int ty = tid / (BN / TN);

    float acc[TM][TN];
#pragma unroll
    for (int i = 0; i < TM; i++)
#pragma unroll
        for (int j = 0; j < TN; j++) acc[i][j] = 0.f;

    for (int k0 = 0; k0 < K; k0 += BK) {
        // load A tile (BM x BK), store transposed
#pragma unroll
        for (int it = 0; it < BM * BK / 1024; ++it) {
            int f = tid + it * 256;
            int row = f / (BK / 4);
            int c4 = f % (BK / 4);
            float4 v = *(const float4*)&A[(long)(m0 + row) * K + k0 + c4 * 4];
            As[c4 * 4 + 0][row] = v.x;
            As[c4 * 4 + 1][row] = v.y;
            As[c4 * 4 + 2][row] = v.z;
            As[c4 * 4 + 3][row] = v.w;
        }
        // load B tile (BK x BN)
#pragma unroll
        for (int it = 0; it < BK * BN / 1024; ++it) {
            int f = tid + it * 256;
            int row = f / (BN / 4);
            int c4 = f % (BN / 4);
            *(float4*)&Bs[row][c4 * 4] =
                *(const float4*)&W[(long)(k0 + row) * N + n0 + c4 * 4];
        }
        __syncthreads();
#pragma unroll
        for (int kk = 0; kk < BK; ++kk) {
            float a[TM], bfrag[TN];
#pragma unroll
            for (int i = 0; i < TM / 4; i++)
                ((float4*)a)[i] = *(const float4*)&As[kk][ty * TM + i * 4];
#pragma unroll
            for (int j = 0; j < TN / 4; j++)
                ((float4*)bfrag)[j] = *(const float4*)&Bs[kk][tx * TN + j * 4];
#pragma unroll
            for (int i = 0; i < TM; i++)
#pragma unroll
                for (int j = 0; j < TN; j++) acc[i][j] += a[i] * bfrag[j];
        }
        __syncthreads();
    }

#pragma unroll
    for (int i = 0; i < TM; i++) {
        int row = m0 + ty * TM + i;
#pragma unroll
        for (int j = 0; j < TN; j++) {
            int col = n0 + tx * TN + j;
            float v = acc[i][j];
            if (EPI >= 1) v += bias[col];
            long idx = (long)row * N + col;
            if (EPI == 2) v += res[idx];
            if (EPI == 3) v = gelu_exact(v);
            C[idx] = v;
        }
    }
}

// --------------- pseudo-token softmax over L + prefix scan ---------------
// one block per (p, b). Produces pAT (B,P,L) and PS (B,P,L+1).
__global__ void __launch_bounds__(256) softmax_scan_kernel(
    const float* __restrict__ pscore, const int* __restrict__ maskPAD,
    float* __restrict__ pAT, float* __restrict__ PS)
{
    const int p = blockIdx.x, b = blockIdx.y;
    const int tid = threadIdx.x;
    __shared__ float red[256];

    float loc[4];
    float mx = -3.0e38f;
#pragma unroll
    for (int i = 0; i < 4; i++) {
        int l = tid * 4 + i;
        float v = pscore[((long)(b * LL + l)) * PP + p];
        if (maskPAD[(long)b * LL * LL + l] == 0) v = -32768.0f;
        loc[i] = v;
        mx = fmaxf(mx, v);
    }
    red[tid] = mx;
    __syncthreads();
    for (int s = 128; s > 0; s >>= 1) {
        if (tid < s) red[tid] = fmaxf(red[tid], red[tid + s]);
        __syncthreads();
    }
    mx = red[0];
    __syncthreads();

    float tsum = 0.f;
#pragma unroll
    for (int i = 0; i < 4; i++) {
        loc[i] = expf(loc[i] - mx);
        tsum += loc[i];
    }
    red[tid] = tsum;
    __syncthreads();
    // Hillis-Steele inclusive scan over thread sums
    for (int off = 1; off < 256; off <<= 1) {
        float t = (tid >= off) ? red[tid - off] : 0.f;
        __syncthreads();
        red[tid] += t;
        __syncthreads();
    }
    float total = red[255];
    float excl = red[tid] - tsum;
    float inv = 1.0f / total;

    float* pa = pAT + ((long)(b * PP + p)) * LL;
    float* ps = PS + ((long)(b * PP + p)) * (LL + 1);
    if (tid == 0) ps[0] = 0.f;
    float run = excl;
#pragma unroll
    for (int i = 0; i < 4; i++) {
        int l = tid * 4 + i;
        pa[l] = loc[i] * inv;
        run += loc[i];
        ps[l + 1] = run * inv;
    }
}

// ------------------------- attention scores -------------------------
// scores[b,h,p,l] = (q[b,l,h,:] . k[b,p,h,:]) / 8
__global__ void __launch_bounds__(256) scores_kernel(
    const float* __restrict__ q, const float* __restrict__ k,
    float* __restrict__ scores)
{
    const int lt = blockIdx.x;  // L/64
    const int h = blockIdx.y, b = blockIdx.z;
    const int l0 = lt * 64;
    const int tid = threadIdx.x;
    __shared__ float sk[64][65];  // [d][p]
    __shared__ float sq[64][65];  // [d][l]

#pragma unroll
    for (int it = 0; it < 4; ++it) {
        int f = tid + it * 256;
        int p = f / 16, d4 = f % 16;
        float4 v = *(const float4*)&k[((long)(b * PP + p)) * HD + h * 64 + d4 * 4];
        sk[d4 * 4 + 0][p] = v.x; sk[d4 * 4 + 1][p] = v.y;
        sk[d4 * 4 + 2][p] = v.z; sk[d4 * 4 + 3][p] = v.w;
    }
#pragma unroll
    for (int it = 0; it < 4; ++it) {
        int f = tid + it * 256;
        int l = f / 16, d4 = f % 16;
        float4 v = *(const float4*)&q[((long)(b * LL + l0 + l)) * HD + h * 64 + d4 * 4];
        sq[d4 * 4 + 0][l] = v.x; sq[d4 * 4 + 1][l] = v.y;
        sq[d4 * 4 + 2][l] = v.z; sq[d4 * 4 + 3][l] = v.w;
    }
    __syncthreads();

    const int ty = tid / 16;  // p group
    const int tx = tid % 16;  // l group
    float acc[4][4] = {};
#pragma unroll
    for (int d = 0; d < 64; d++) {
        float a[4], bb[4];
#pragma unroll
        for (int i = 0; i < 4; i++) a[i] = sk[d][ty * 4 + i];
#pragma unroll
        for (int j = 0; j < 4; j++) bb[j] = sq[d][tx * 4 + j];
#pragma unroll
        for (int i = 0; i < 4; i++)
#pragma unroll
            for (int j = 0; j < 4; j++) acc[i][j] += a[i] * bb[j];
    }
#pragma unroll
    for (int i = 0; i < 4; i++) {
        int p = ty * 4 + i;
#pragma unroll
        for (int j = 0; j < 4; j++) {
            int l = tx * 4 + j;
            scores[(((long)(b * HH + h)) * PP + p) * LL + l0 + l] = acc[i][j] * 0.125f;
        }
    }
}

// ------------------------- relative-position bias -------------------------
// scores[b,h,p,l] = scores*Kb + bb where Kb/bb come from 15 banded sums of pA.
__global__ void __launch_bounds__(256) relbias_kernel(
    const float* __restrict__ PS, const float* __restrict__ pAT,
    const float* __restrict__ embK, const float* __restrict__ embB,
    float* __restrict__ scores)
{
    const int l = blockIdx.x * 256 + threadIdx.x;
    const int p = blockIdx.y, b = blockIdx.z;
    __shared__ float sK[120], sB[120];
    if (threadIdx.x < 120) {
        sK[threadIdx.x] = embK[threadIdx.x];
        sB[threadIdx.x] = embB[threadIdx.x];
    }
    __syncthreads();

    const float* ps = PS + ((long)(b * PP + p)) * (LL + 1);
    float S[15];
    S[0] = pAT[((long)(b * PP + p)) * LL + l];
#pragma unroll
    for (int t = 1; t < 15; t++) {
        int lo = c_lo[t], hi = c_hi[t];
        float s = 0.f;
        int a1 = l - lo;
        if (a1 >= 0) {
            int a0 = l - hi; if (a0 < 0) a0 = 0;
            s += ps[a1 + 1] - ps[a0];
        }
        int b0 = l + lo;
        if (b0 < LL) {
            int b1 = l + hi; if (b1 > LL - 1) b1 = LL - 1;
            s += ps[b1 + 1] - ps[b0];
        }
        S[t] = s;
    }
#pragma unroll
    for (int h = 0; h < HH; h++) {
        float kb = 0.f, bb = 0.f;
#pragma unroll
        for (int t = 0; t < 15; t++) {
            kb += S[t] * sK[t * HH + h];
            bb += S[t] * sB[t * HH + h];
        }
        long idx = (((long)(b * HH + h)) * PP + p) * LL + l;
        scores[idx] = scores[idx] * kb + bb;
    }
}

// ------------------------- softmax over P (=64) -------------------------
__global__ void __launch_bounds__(256) softmaxP_kernel(float* __restrict__ scores)
{
    const long l = blockIdx.x * 256 + threadIdx.x;
    const int bh = blockIdx.y;
    float* base = scores + (long)bh * PP * LL + l;
    float v[PP];
    float mx = -3.0e38f;
#pragma unroll
    for (int p = 0; p < PP; p++) {
        v[p] = base[(long)p * LL];
        mx = fmaxf(mx, v[p]);
    }
    float s = 0.f;
#pragma unroll
    for (int p = 0; p < PP; p++) {
        v[p] = expf(v[p] - mx);
        s += v[p];
    }
    float inv = 1.0f / s;
#pragma unroll
    for (int p = 0; p < PP; p++) base[(long)p * LL] = v[p] * inv;
}

// ------------------------- z = alpha @ v -------------------------
// z[b, l, h*64+d] = sum_p alpha[b,h,p,l] * v[b,p,h*64+d]
__global__ void __launch_bounds__(256) zhead_kernel(
    const float* __restrict__ alpha, const float* __restrict__ v,
    float* __restrict__ z)
{
    const int lt = blockIdx.x;
    const int h = blockIdx.y, b = blockIdx.z;
    const int l0 = lt * 64;
    const int tid = threadIdx.x;
    __shared__ float sa[64][64];  // [p][l]
    __shared__ float sv[64][64];  // [p][d]

#pragma unroll
    for (int it = 0; it < 4; ++it) {
        int f = tid + it * 256;
        int p = f / 16, l4 = f % 16;
        *(float4*)&sa[p][l4 * 4] =
            *(const float4*)&alpha[(((long)(b * HH + h)) * PP + p) * LL + l0 + l4 * 4];
    }
#pragma unroll
    for (int it = 0; it < 4; ++it) {
        int f = tid + it * 256;
        int p = f / 16, d4 = f % 16;
        *(float4*)&sv[p][d4 * 4] =
            *(const float4*)&v[((long)(b * PP + p)) * HD + h * 64 + d4 * 4];
    }
    __syncthreads();

    const int ty = tid / 16;  // l group
    const int tx = tid % 16;  // d group
    float acc[4][4] = {};
#pragma unroll
    for (int p = 0; p < 64; p++) {
        float a[4], bb[4];
#pragma unroll
        for (int i = 0; i < 4; i++) a[i] = sa[p][ty * 4 + i];
#pragma unroll
        for (int j = 0; j < 4; j++) bb[j] = sv[p][tx * 4 + j];
#pragma unroll
        for (int i = 0; i < 4; i++)
#pragma unroll
            for (int j = 0; j < 4; j++) acc[i][j] += a[i] * bb[j];
    }
#pragma unroll
    for (int i = 0; i < 4; i++) {
        int l = l0 + ty * 4 + i;
#pragma unroll
        for (int j = 0; j < 4; j++) {
            z[((long)(b * LL + l)) * HD + h * 64 + tx * 4 + j] = acc[i][j];
        }
    }
}

// ------------------------- layernorm (row of 512) -------------------------
__global__ void __launch_bounds__(256) ln_kernel(
    const float* __restrict__ x, const float* __restrict__ g,
    const float* __restrict__ b, float* __restrict__ out)
{
    const int row = blockIdx.x;
    const int tid = threadIdx.x;
    __shared__ float red[256];
    float2 v = ((const float2*)(x + (long)row * CC))[tid];

    red[tid] = v.x + v.y;
    __syncthreads();
    for (int s = 128; s > 0; s >>= 1) {
        if (tid < s) red[tid] += red[tid + s];
        __syncthreads();
    }
    float mean = red[0] * (1.0f / CC);
    __syncthreads();

    float dx = v.x - mean, dy = v.y - mean;
    red[tid] = dx * dx + dy * dy;
    __syncthreads();
    for (int s = 128; s > 0; s >>= 1) {
        if (tid < s) red[tid] += red[tid + s];
        __syncthreads();
    }
    float var = red[0] * (1.0f / CC);
    float rstd = rsqrtf(var + 1e-5f);

    int c = tid * 2;
    float2 o;
    o.x = dx * rstd * g[c] + b[c];
    o.y = dy * rstd * g[c + 1] + b[c + 1];
    ((float2*)(out + (long)row * CC))[tid] = o;
}

// ------------------------- host launch -------------------------
extern "C" void kernel_launch(void* const* d_in, const int* in_sizes, int n_in,
                              void* d_out, int out_size)
{
    const float* qx = (const float*)d_in[0];
    const float* kx = (const float*)d_in[1];
    const float* vx = (const float*)d_in[2];
    const int* maskPAD = (const int*)d_in[3];
    const float* Wp = (const float*)d_in[4];
    const float* bp = (const float*)d_in[5];
    const float* WQ = (const float*)d_in[6];
    const float* bQ = (const float*)d_in[7];
    const float* WK = (const float*)d_in[8];
    const float* bK = (const float*)d_in[9];
    const float* WV = (const float*)d_in[10];
    const float* bV = (const float*)d_in[11];
    const float* WO = (const float*)d_in[12];
    const float* bO = (const float*)d_in[13];
    const float* embK = (const float*)d_in[14];
    const float* embB = (const float*)d_in[15];
    const float* ln1_g = (const float*)d_in[16];
    const float* ln1_b = (const float*)d_in[17];
    const float* ln2_g = (const float*)d_in[18];
    const float* ln2_b = (const float*)d_in[19];
    const float* W1 = (const float*)d_in[20];
    const float* b1 = (const float*)d_in[21];
    const float* W2 = (const float*)d_in[22];
    const float* b2 = (const float*)d_in[23];
    float* out = (float*)d_out;

    float *d_pscore, *d_pAT, *d_PS, *d_kxp, *d_vxp, *d_q, *d_k, *d_v;
    float *d_scores, *d_z, *d_y1, *d_z1, *d_h1, *d_y2;
    cudaGetSymbolAddress((void**)&d_pscore, g_pscore);
    cudaGetSymbolAddress((void**)&d_pAT, g_pAT);
    cudaGetSymbolAddress((void**)&d_PS, g_PS);
    cudaGetSymbolAddress((void**)&d_kxp, g_kxp);
    cudaGetSymbolAddress((void**)&d_vxp, g_vxp);
    cudaGetSymbolAddress((void**)&d_q, g_q);
    cudaGetSymbolAddress((void**)&d_k, g_k);
    cudaGetSymbolAddress((void**)&d_v, g_v);
    cudaGetSymbolAddress((void**)&d_scores, g_scores);
    cudaGetSymbolAddress((void**)&d_z, g_z);
    cudaGetSymbolAddress((void**)&d_y1, g_y1);
    cudaGetSymbolAddress((void**)&d_z1, g_z1);
    cudaGetSymbolAddress((void**)&d_h1, g_h1);
    cudaGetSymbolAddress((void**)&d_y2, g_y2);

    const int M = BB * LL;  // 16384

    // 1) pScore = vx @ Wp + bp           (16384 x 64, K=512)
    sgemm<128, 64, 16, 8, 4, 1><<<dim3(1, M / 128, 1), 256>>>(
        vx, Wp, bp, nullptr, d_pscore, M, PP, CC, 0, 0, 0);

    // 2) softmax over L + prefix scan
    softmax_scan_kernel<<<dim3(PP, BB), 256>>>(d_pscore, maskPAD, d_pAT, d_PS);

    // 3,4) kxp/vxp = pAT @ {kx,vx}       (batched: 64 x 512, K=1024)
    sgemm<64, 64, 16, 4, 4, 0><<<dim3(CC / 64, 1, BB), 256>>>(
        d_pAT, kx, nullptr, nullptr, d_kxp, PP, CC, LL,
        (long)PP * LL, (long)LL * CC, (long)PP * CC);
    sgemm<64, 64, 16, 4, 4, 0><<<dim3(CC / 64, 1, BB), 256>>>(
        d_pAT, vx, nullptr, nullptr, d_vxp, PP, CC, LL,
        (long)PP * LL, (long)LL * CC, (long)PP * CC);

    // 5) q = qx @ WQ + bQ                (16384 x 512, K=512)
    sgemm<128, 128, 16, 8, 8, 1><<<dim3(HD / 128, M / 128, 1), 256>>>(
        qx, WQ, bQ, nullptr, d_q, M, HD, CC, 0, 0, 0);

    // 6,7) k/v = kxp/vxp @ WK/WV + b     (1024 x 512, K=512)
    sgemm<128, 128, 16, 8, 8, 1><<<dim3(HD / 128, (BB * PP) / 128, 1), 256>>>(
        d_kxp, WK, bK, nullptr, d_k, BB * PP, HD, CC, 0, 0, 0);
    sgemm<128, 128, 16, 8, 8, 1><<<dim3(HD / 128, (BB * PP) / 128, 1), 256>>>(
        d_vxp, WV, bV, nullptr, d_v, BB * PP, HD, CC, 0, 0, 0);

    // 8) scores (B,H,P,L)
    scores_kernel<<<dim3(LL / 64, HH, BB), 256>>>(d_q, d_k, d_scores);

    // 9) relative-position bias via banded prefix sums
    relbias_kernel<<<dim3(LL / 256, PP, BB), 256>>>(d_PS, d_pAT, embK, embB, d_scores);

    // 10) softmax over P
    softmaxP_kernel<<<dim3(LL / 256, BB * HH), 256>>>(d_scores);

    // 11) z = alpha @ v
    zhead_kernel<<<dim3(LL / 64, HH, BB), 256>>>(d_scores, d_v, d_z);

    // 12) y1 = z @ WO + bO + vx
    sgemm<128, 128, 16, 8, 8, 2><<<dim3(CC / 128, M / 128, 1), 256>>>(
        d_z, WO, bO, vx, d_y1, M, CC, HD, 0, 0, 0);

    // 13) z1 = LN1(y1)
    ln_kernel<<<M, 256>>>(d_y1, ln1_g, ln1_b, d_z1);

    // 14) h1 = gelu(z1 @ W1 + b1)        (16384 x 2048, K=512)
    sgemm<128, 128, 16, 8, 8, 3><<<dim3(FF / 128, M / 128, 1), 256>>>(
        d_z1, W1, b1, nullptr, d_h1, M, FF, CC, 0, 0, 0);

    // 15) y2 = h1 @ W2 + b2 + z1         (16384 x 512, K=2048)
    sgemm<128, 128, 16, 8, 8, 2><<<dim3(CC / 128, M / 128, 1), 256>>>(
        d_h1, W2, b2, d_z1, d_y2, M, CC, FF, 0, 0, 0);

    // 16) out = LN2(y2)
    ln_kernel<<<M, 256>>>(d_y2, ln2_g, ln2_b, out);
}